// round 1
// baseline (speedup 1.0000x reference)
#include <cuda_runtime.h>
#include <math.h>

#define DIM 128
#define NH 4
#define MAXN 50048
#define MAXE 800032

// ---------------- scratch (static device globals; no allocation) ----------------
__device__ float g_hs[MAXN * DIM];      // hs = x_src @ Wsrc for current relation
__device__ float g_hfood[MAXN * DIM];   // layer-1 food output
__device__ float g_hnut[MAXN * DIM];    // layer-1 nut output
__device__ float g_asA[MAXN * NH];      // alpha_src, relation fn
__device__ float g_adA[MAXN * NH];      // alpha_dst, relation fn
__device__ float g_asB[MAXN * NH];      // alpha_src, relation nf
__device__ float g_adB[MAXN * NH];      // alpha_dst, relation nf
__device__ float g_m[MAXN * NH];        // softmax max per (dst,h)
__device__ float g_r[MAXN * NH];        // 1/(denom+1e-16) per (dst,h)
__device__ float g_uv[4096];            // folded attention vectors [l][rel][s/d][k][h]
__device__ int   g_deg[MAXN];
__device__ int   g_cur[MAXN];
__device__ int   g_offA[MAXN + 1];      // CSR offsets, dst = nutrient (ei_fn)
__device__ int   g_offB[MAXN + 1];      // CSR offsets, dst = food (ei_nf)
__device__ int   g_srcA[MAXE];          // CSR src ids (sorted per bucket)
__device__ int   g_srcB[MAXE];

// ---------------- CSR build ----------------
__global__ void histK(const int* __restrict__ dst, int* __restrict__ deg, int E) {
    int i = blockIdx.x * blockDim.x + threadIdx.x;
    int stride = gridDim.x * blockDim.x;
    for (; i < E; i += stride) atomicAdd(&deg[dst[i]], 1);
}

// single-block exclusive scan over n degrees -> off[0..n], off[n] = total
__global__ void scanK(const int* __restrict__ deg, int* __restrict__ off, int n) {
    __shared__ int sh[1024];
    int t = threadIdx.x;
    int chunk = (n + 1023) / 1024;
    int start = t * chunk;
    int mySum = 0;
    for (int i = 0; i < chunk; i++) {
        int idx = start + i;
        if (idx < n) mySum += deg[idx];
    }
    sh[t] = mySum;
    __syncthreads();
    for (int d = 1; d < 1024; d <<= 1) {
        int v = 0;
        if (t >= d) v = sh[t - d];
        __syncthreads();
        if (t >= d) sh[t] += v;
        __syncthreads();
    }
    int run = sh[t] - mySum;  // exclusive prefix for this thread's chunk
    for (int i = 0; i < chunk; i++) {
        int idx = start + i;
        if (idx < n) { off[idx] = run; run += deg[idx]; }
    }
    if (t == 0) off[n] = sh[1023];
}

__global__ void initCurK(const int* __restrict__ off, int* __restrict__ cur, int n) {
    int i = blockIdx.x * blockDim.x + threadIdx.x;
    if (i < n) cur[i] = off[i];
}

__global__ void fillK(const int* __restrict__ src, const int* __restrict__ dst,
                      int* __restrict__ cur, int* __restrict__ csrc, int E) {
    int i = blockIdx.x * blockDim.x + threadIdx.x;
    int stride = gridDim.x * blockDim.x;
    for (; i < E; i += stride) {
        int pos = atomicAdd(&cur[dst[i]], 1);
        csrc[pos] = src[i];
    }
}

// sort each dst bucket by src id -> deterministic accumulation order
__global__ void sortK(const int* __restrict__ off, int* __restrict__ csrc, int n) {
    int d = blockIdx.x * blockDim.x + threadIdx.x;
    if (d >= n) return;
    int beg = off[d], end = off[d + 1];
    int cnt = end - beg;
    if (cnt <= 1) return;
    if (cnt <= 96) {
        int buf[96];
        for (int i = 0; i < cnt; i++) buf[i] = csrc[beg + i];
        for (int i = 1; i < cnt; i++) {
            int key = buf[i];
            int j = i - 1;
            while (j >= 0 && buf[j] > key) { buf[j + 1] = buf[j]; j--; }
            buf[j + 1] = key;
        }
        for (int i = 0; i < cnt; i++) csrc[beg + i] = buf[i];
    } else {
        for (int i = beg + 1; i < end; i++) {
            int key = csrc[i];
            int j = i - 1;
            while (j >= beg && csrc[j] > key) { csrc[j + 1] = csrc[j]; j--; }
            csrc[j + 1] = key;
        }
    }
}

// ---------------- folded attention vectors ----------------
// uv[(((l*2+rel)*2+sv)*128 + k)*4 + h] = sum_c W[l][k][h*32+c] * att[l][h][c]
__global__ void uvK(const float* __restrict__ WsrcFN, const float* __restrict__ WdstFN,
                    const float* __restrict__ aSrcFN, const float* __restrict__ aDstFN,
                    const float* __restrict__ WsrcNF, const float* __restrict__ WdstNF,
                    const float* __restrict__ aSrcNF, const float* __restrict__ aDstNF,
                    float* __restrict__ uv) {
    int t = blockIdx.x * blockDim.x + threadIdx.x;
    if (t >= 4096) return;
    int h = t & 3;
    int k = (t >> 2) & 127;
    int sv = (t >> 9) & 1;
    int rel = (t >> 10) & 1;
    int l = (t >> 11) & 1;
    const float* W;
    const float* att;
    if (rel == 0) { W = sv ? WdstFN : WsrcFN; att = sv ? aDstFN : aSrcFN; }
    else          { W = sv ? WdstNF : WsrcNF; att = sv ? aDstNF : aSrcNF; }
    W += l * DIM * DIM;
    att += l * NH * 32;
    float sum = 0.f;
    #pragma unroll 8
    for (int c = 0; c < 32; c++)
        sum += W[k * DIM + h * 32 + c] * att[h * 32 + c];
    uv[t] = sum;
}

// ---------------- alpha projections: as = x @ v, ad = x @ u ----------------
__global__ void alphaK(const float4* __restrict__ x, const float* __restrict__ vmat,
                       const float* __restrict__ umat, float4* __restrict__ asOut,
                       float4* __restrict__ adOut, int n) {
    __shared__ float sv[512];
    __shared__ float su[512];
    int t = threadIdx.x;
    for (int i = t; i < 512; i += blockDim.x) { sv[i] = vmat[i]; su[i] = umat[i]; }
    __syncthreads();
    int warp = (blockIdx.x * blockDim.x + t) >> 5;
    int lane = t & 31;
    if (warp >= n) return;
    float4 xv = x[warp * 32 + lane];
    float xj[4] = {xv.x, xv.y, xv.z, xv.w};
    float pa[4] = {0, 0, 0, 0}, pd[4] = {0, 0, 0, 0};
    int j0 = lane * 4;
    #pragma unroll
    for (int j = 0; j < 4; j++) {
        #pragma unroll
        for (int h = 0; h < 4; h++) {
            pa[h] += xj[j] * sv[(j0 + j) * 4 + h];
            pd[h] += xj[j] * su[(j0 + j) * 4 + h];
        }
    }
    #pragma unroll
    for (int o = 16; o > 0; o >>= 1) {
        #pragma unroll
        for (int h = 0; h < 4; h++) {
            pa[h] += __shfl_down_sync(0xffffffffu, pa[h], o);
            pd[h] += __shfl_down_sync(0xffffffffu, pd[h], o);
        }
    }
    if (lane == 0) {
        asOut[warp] = make_float4(pa[0], pa[1], pa[2], pa[3]);
        adOut[warp] = make_float4(pd[0], pd[1], pd[2], pd[3]);
    }
}

// ---------------- GEMM: C[M,128] = A[M,128] @ W[128,128] ----------------
__global__ void __launch_bounds__(256, 2)
gemmK(const float* __restrict__ A, const float* __restrict__ W,
      float* __restrict__ C, int M) {
    __shared__ float As[16][132];
    __shared__ float Bs[16][128];
    int t = threadIdx.x;
    int tx = t & 15, ty = t >> 4;
    int rowBase = blockIdx.x * 128;
    float acc[8][8];
    #pragma unroll
    for (int i = 0; i < 8; i++)
        #pragma unroll
        for (int j = 0; j < 8; j++) acc[i][j] = 0.f;

    for (int kk = 0; kk < DIM; kk += 16) {
        #pragma unroll
        for (int i = 0; i < 2; i++) {
            int f = t + i * 256;
            int r = f >> 2;
            int c4 = (f & 3) * 4;
            float4 v = make_float4(0, 0, 0, 0);
            int gr = rowBase + r;
            if (gr < M) v = *(const float4*)(A + gr * DIM + kk + c4);
            As[c4 + 0][r] = v.x;
            As[c4 + 1][r] = v.y;
            As[c4 + 2][r] = v.z;
            As[c4 + 3][r] = v.w;
        }
        #pragma unroll
        for (int i = 0; i < 2; i++) {
            int f = t + i * 256;
            int kr = f >> 5;
            int n4 = (f & 31) * 4;
            *(float4*)(&Bs[kr][n4]) = *(const float4*)(W + (kk + kr) * DIM + n4);
        }
        __syncthreads();
        #pragma unroll
        for (int k = 0; k < 16; k++) {
            float a[8], b[8];
            *(float4*)(a)     = *(float4*)(&As[k][ty * 8]);
            *(float4*)(a + 4) = *(float4*)(&As[k][ty * 8 + 4]);
            *(float4*)(b)     = *(float4*)(&Bs[k][tx * 8]);
            *(float4*)(b + 4) = *(float4*)(&Bs[k][tx * 8 + 4]);
            #pragma unroll
            for (int i = 0; i < 8; i++)
                #pragma unroll
                for (int j = 0; j < 8; j++) acc[i][j] += a[i] * b[j];
        }
        __syncthreads();
    }
    #pragma unroll
    for (int i = 0; i < 8; i++) {
        int gr = rowBase + ty * 8 + i;
        if (gr < M) {
            float4 v0 = make_float4(acc[i][0], acc[i][1], acc[i][2], acc[i][3]);
            float4 v1 = make_float4(acc[i][4], acc[i][5], acc[i][6], acc[i][7]);
            *(float4*)(C + gr * DIM + tx * 8) = v0;
            *(float4*)(C + gr * DIM + tx * 8 + 4) = v1;
        }
    }
}

// ---------------- per-dst online softmax stats ----------------
__global__ void statsK(const int* __restrict__ off, const int* __restrict__ csrc,
                       const float4* __restrict__ as, const float4* __restrict__ ad,
                       float4* __restrict__ mOut, float4* __restrict__ rOut, int n) {
    int d = blockIdx.x * blockDim.x + threadIdx.x;
    if (d >= n) return;
    float4 a = ad[d];
    float adv[4] = {a.x, a.y, a.z, a.w};
    float m[4] = {-1e30f, -1e30f, -1e30f, -1e30f};
    float s[4] = {0, 0, 0, 0};
    int beg = off[d], end = off[d + 1];
    for (int e = beg; e < end; e++) {
        float4 sv = as[csrc[e]];
        float ev[4] = {sv.x + adv[0], sv.y + adv[1], sv.z + adv[2], sv.w + adv[3]};
        #pragma unroll
        for (int h = 0; h < 4; h++) {
            float eh = ev[h] > 0.f ? ev[h] : 0.2f * ev[h];
            if (eh > m[h]) {
                s[h] = s[h] * __expf(m[h] - eh) + 1.f;
                m[h] = eh;
            } else {
                s[h] += __expf(eh - m[h]);
            }
        }
    }
    mOut[d] = make_float4(m[0], m[1], m[2], m[3]);
    rOut[d] = make_float4(1.f / (s[0] + 1e-16f), 1.f / (s[1] + 1e-16f),
                          1.f / (s[2] + 1e-16f), 1.f / (s[3] + 1e-16f));
}

// ---------------- warp-per-dst aggregation + bias + ELU ----------------
__global__ void aggK(const int* __restrict__ off, const int* __restrict__ csrc,
                     const float* __restrict__ as, const float* __restrict__ ad,
                     const float* __restrict__ m, const float* __restrict__ r,
                     const float4* __restrict__ hs, const float* __restrict__ bias,
                     float4* __restrict__ out, int n) {
    int warp = (blockIdx.x * blockDim.x + threadIdx.x) >> 5;
    int lane = threadIdx.x & 31;
    if (warp >= n) return;
    int d = warp;
    int h = lane >> 3;
    float adh = ad[d * 4 + h];
    float mh = m[d * 4 + h];
    float rh = r[d * 4 + h];
    float4 acc = make_float4(0, 0, 0, 0);
    int beg = off[d], end = off[d + 1];
    for (int e = beg; e < end; e++) {
        int s = csrc[e];
        float asv = __ldg(&as[s * 4 + h]);
        float ee = asv + adh;
        ee = ee > 0.f ? ee : 0.2f * ee;
        float w = __expf(ee - mh) * rh;
        float4 hv = hs[s * 32 + lane];
        acc.x += w * hv.x;
        acc.y += w * hv.y;
        acc.z += w * hv.z;
        acc.w += w * hv.w;
    }
    float4 b = *(const float4*)(bias + lane * 4);
    acc.x += b.x; acc.y += b.y; acc.z += b.z; acc.w += b.w;
    acc.x = acc.x > 0.f ? acc.x : expm1f(acc.x);
    acc.y = acc.y > 0.f ? acc.y : expm1f(acc.y);
    acc.z = acc.z > 0.f ? acc.z : expm1f(acc.z);
    acc.w = acc.w > 0.f ? acc.w : expm1f(acc.w);
    out[d * 32 + lane] = acc;
}

// ---------------- driver ----------------
extern "C" void kernel_launch(void* const* d_in, const int* in_sizes, int n_in,
                              void* d_out, int out_size) {
    const float* x_food  = (const float*)d_in[0];
    const float* x_nut   = (const float*)d_in[1];
    const float* WsrcFN  = (const float*)d_in[2];
    const float* WdstFN  = (const float*)d_in[3];
    const float* aSrcFN  = (const float*)d_in[4];
    const float* aDstFN  = (const float*)d_in[5];
    const float* biasFN  = (const float*)d_in[6];
    const float* WsrcNF  = (const float*)d_in[7];
    const float* WdstNF  = (const float*)d_in[8];
    const float* aSrcNF  = (const float*)d_in[9];
    const float* aDstNF  = (const float*)d_in[10];
    const float* biasNF  = (const float*)d_in[11];
    const int*   ei_fn   = (const int*)d_in[12];
    const int*   ei_nf   = (const int*)d_in[13];
    float* out = (float*)d_out;

    int NF = in_sizes[0] / DIM;
    int NN = in_sizes[1] / DIM;
    int E  = in_sizes[12] / 2;

    float *hs, *hfood, *hnut, *asA, *adA, *asB, *adB, *mArr, *rArr, *uv;
    int *deg, *cur, *offA, *offB, *srcA, *srcB;
    cudaGetSymbolAddress((void**)&hs, g_hs);
    cudaGetSymbolAddress((void**)&hfood, g_hfood);
    cudaGetSymbolAddress((void**)&hnut, g_hnut);
    cudaGetSymbolAddress((void**)&asA, g_asA);
    cudaGetSymbolAddress((void**)&adA, g_adA);
    cudaGetSymbolAddress((void**)&asB, g_asB);
    cudaGetSymbolAddress((void**)&adB, g_adB);
    cudaGetSymbolAddress((void**)&mArr, g_m);
    cudaGetSymbolAddress((void**)&rArr, g_r);
    cudaGetSymbolAddress((void**)&uv, g_uv);
    cudaGetSymbolAddress((void**)&deg, g_deg);
    cudaGetSymbolAddress((void**)&cur, g_cur);
    cudaGetSymbolAddress((void**)&offA, g_offA);
    cudaGetSymbolAddress((void**)&offB, g_offB);
    cudaGetSymbolAddress((void**)&srcA, g_srcA);
    cudaGetSymbolAddress((void**)&srcB, g_srcB);

    int nodeBlk256_NN = (NN + 255) / 256;
    int nodeBlk256_NF = (NF + 255) / 256;
    int warpBlk_NN = (NN + 7) / 8;       // 8 warps per 256-thread block
    int warpBlk_NF = (NF + 7) / 8;
    int gemmBlk_NF = (NF + 127) / 128;
    int gemmBlk_NN = (NN + 127) / 128;

    // CSR for relation fn (dst = nutrient)
    cudaMemsetAsync(deg, 0, NN * sizeof(int));
    histK<<<1024, 256>>>(ei_fn + E, deg, E);
    scanK<<<1, 1024>>>(deg, offA, NN);
    initCurK<<<nodeBlk256_NN, 256>>>(offA, cur, NN);
    fillK<<<1024, 256>>>(ei_fn, ei_fn + E, cur, srcA, E);
    sortK<<<nodeBlk256_NN, 256>>>(offA, srcA, NN);

    // CSR for relation nf (dst = food)
    cudaMemsetAsync(deg, 0, NF * sizeof(int));
    histK<<<1024, 256>>>(ei_nf + E, deg, E);
    scanK<<<1, 1024>>>(deg, offB, NF);
    initCurK<<<nodeBlk256_NF, 256>>>(offB, cur, NF);
    fillK<<<1024, 256>>>(ei_nf, ei_nf + E, cur, srcB, E);
    sortK<<<nodeBlk256_NF, 256>>>(offB, srcB, NF);

    uvK<<<16, 256>>>(WsrcFN, WdstFN, aSrcFN, aDstFN, WsrcNF, WdstNF, aSrcNF, aDstNF, uv);

    for (int l = 0; l < 2; l++) {
        const float* inF = l ? hfood : x_food;
        const float* inN = l ? hnut : x_nut;
        float* outF = l ? out : hfood;
        float* outN = l ? out + (size_t)NF * DIM : hnut;
        // uv offsets: (l,rel,sv) -> l*2048 + rel*1024 + sv*512
        const float* v_fn = uv + l * 2048 + 0 * 1024 + 0 * 512;
        const float* u_fn = uv + l * 2048 + 0 * 1024 + 1 * 512;
        const float* v_nf = uv + l * 2048 + 1 * 1024 + 0 * 512;
        const float* u_nf = uv + l * 2048 + 1 * 1024 + 1 * 512;

        // alpha projections: food nodes -> as_fn (v_fn) & ad_nf (u_nf); nut nodes -> as_nf & ad_fn
        alphaK<<<warpBlk_NF, 256>>>((const float4*)inF, v_fn, u_nf,
                                    (float4*)asA, (float4*)adB, NF);
        alphaK<<<warpBlk_NN, 256>>>((const float4*)inN, v_nf, u_fn,
                                    (float4*)asB, (float4*)adA, NN);

        // relation fn: food -> nutrient
        gemmK<<<gemmBlk_NF, 256>>>(inF, WsrcFN + l * DIM * DIM, hs, NF);
        statsK<<<nodeBlk256_NN, 256>>>(offA, srcA, (const float4*)asA, (const float4*)adA,
                                       (float4*)mArr, (float4*)rArr, NN);
        aggK<<<warpBlk_NN, 256>>>(offA, srcA, asA, adA, mArr, rArr,
                                  (const float4*)hs, biasFN + l * DIM, (float4*)outN, NN);

        // relation nf: nutrient -> food
        gemmK<<<gemmBlk_NN, 256>>>(inN, WsrcNF + l * DIM * DIM, hs, NN);
        statsK<<<nodeBlk256_NF, 256>>>(offB, srcB, (const float4*)asB, (const float4*)adB,
                                       (float4*)mArr, (float4*)rArr, NF);
        aggK<<<warpBlk_NF, 256>>>(offB, srcB, asB, adB, mArr, rArr,
                                  (const float4*)hs, biasNF + l * DIM, (float4*)outF, NF);
    }
}

// round 2
// speedup vs baseline: 1.1512x; 1.1512x over previous
#include <cuda_runtime.h>
#include <cuda_fp16.h>
#include <math.h>

#define DIM 128
#define NH 4
#define MAXN 50048
#define MAXE 800032
#define MAXDEG 96

// ---------------- scratch (static device globals; no allocation) ----------------
__device__ __half g_hs[MAXN * DIM];     // hs = x_src @ Wsrc (fp16 messages)
__device__ float g_hfood[MAXN * DIM];   // layer-1 food output
__device__ float g_hnut[MAXN * DIM];    // layer-1 nut output
__device__ float g_asA[MAXN * NH];      // alpha_src, relation fn
__device__ float g_adA[MAXN * NH];      // alpha_dst, relation fn
__device__ float g_asB[MAXN * NH];      // alpha_src, relation nf
__device__ float g_adB[MAXN * NH];      // alpha_dst, relation nf
__device__ float g_uv[4096];            // folded attention vectors [l][rel][s/d][k][h]
__device__ int   g_deg[2 * MAXN];
__device__ int   g_cur[2 * MAXN];
__device__ int   g_offA[MAXN + 1];      // CSR offsets, dst = nutrient (ei_fn)
__device__ int   g_offB[MAXN + 1];      // CSR offsets, dst = food (ei_nf)
__device__ int   g_srcA[MAXE];          // CSR src ids (sorted per bucket)
__device__ int   g_srcB[MAXE];

// ---------------- CSR build (both relations in one pass) ----------------
__global__ void histK2(const int* __restrict__ dstA, const int* __restrict__ dstB,
                       int* __restrict__ degA, int* __restrict__ degB, int E) {
    int i = blockIdx.x * blockDim.x + threadIdx.x;
    int stride = gridDim.x * blockDim.x;
    for (; i < 2 * E; i += stride) {
        if (i < E) atomicAdd(&degA[dstA[i]], 1);
        else       atomicAdd(&degB[dstB[i - E]], 1);
    }
}

// 2 blocks: block 0 scans relation A, block 1 relation B. Writes off AND cur.
__global__ void scan2K(const int* __restrict__ degA, int* __restrict__ offA, int* __restrict__ curA, int nA,
                       const int* __restrict__ degB, int* __restrict__ offB, int* __restrict__ curB, int nB) {
    __shared__ int sh[1024];
    const int* deg = blockIdx.x ? degB : degA;
    int* off = blockIdx.x ? offB : offA;
    int* cur = blockIdx.x ? curB : curA;
    int n = blockIdx.x ? nB : nA;
    int t = threadIdx.x;
    int chunk = (n + 1023) / 1024;
    int start = t * chunk;
    int mySum = 0;
    for (int i = 0; i < chunk; i++) {
        int idx = start + i;
        if (idx < n) mySum += deg[idx];
    }
    sh[t] = mySum;
    __syncthreads();
    for (int d = 1; d < 1024; d <<= 1) {
        int v = 0;
        if (t >= d) v = sh[t - d];
        __syncthreads();
        if (t >= d) sh[t] += v;
        __syncthreads();
    }
    int run = sh[t] - mySum;
    for (int i = 0; i < chunk; i++) {
        int idx = start + i;
        if (idx < n) { off[idx] = run; cur[idx] = run; run += deg[idx]; }
    }
    if (t == 0) off[n] = sh[1023];
}

__global__ void fillK2(const int* __restrict__ eiA, const int* __restrict__ eiB,
                       int* __restrict__ curA, int* __restrict__ curB,
                       int* __restrict__ srcA, int* __restrict__ srcB, int E) {
    int i = blockIdx.x * blockDim.x + threadIdx.x;
    int stride = gridDim.x * blockDim.x;
    for (; i < 2 * E; i += stride) {
        if (i < E) {
            int pos = atomicAdd(&curA[eiA[E + i]], 1);
            srcA[pos] = eiA[i];
        } else {
            int j = i - E;
            int pos = atomicAdd(&curB[eiB[E + j]], 1);
            srcB[pos] = eiB[j];
        }
    }
}

// sort each dst bucket by src id -> deterministic accumulation order
__global__ void sortK2(const int* __restrict__ offA, int* __restrict__ srcA, int nA,
                       const int* __restrict__ offB, int* __restrict__ srcB, int nB) {
    int d = blockIdx.x * blockDim.x + threadIdx.x;
    const int* off; int* csrc;
    if (d < nA) { off = offA; csrc = srcA; }
    else if (d < nA + nB) { off = offB; csrc = srcB; d -= nA; }
    else return;
    int beg = off[d], end = off[d + 1];
    int cnt = end - beg;
    if (cnt <= 1) return;
    if (cnt <= MAXDEG) {
        int buf[MAXDEG];
        for (int i = 0; i < cnt; i++) buf[i] = csrc[beg + i];
        for (int i = 1; i < cnt; i++) {
            int key = buf[i];
            int j = i - 1;
            while (j >= 0 && buf[j] > key) { buf[j + 1] = buf[j]; j--; }
            buf[j + 1] = key;
        }
        for (int i = 0; i < cnt; i++) csrc[beg + i] = buf[i];
    } else {
        for (int i = beg + 1; i < end; i++) {
            int key = csrc[i];
            int j = i - 1;
            while (j >= beg && csrc[j] > key) { csrc[j + 1] = csrc[j]; j--; }
            csrc[j + 1] = key;
        }
    }
}

// ---------------- folded attention vectors ----------------
__global__ void uvK(const float* __restrict__ WsrcFN, const float* __restrict__ WdstFN,
                    const float* __restrict__ aSrcFN, const float* __restrict__ aDstFN,
                    const float* __restrict__ WsrcNF, const float* __restrict__ WdstNF,
                    const float* __restrict__ aSrcNF, const float* __restrict__ aDstNF,
                    float* __restrict__ uv) {
    int t = blockIdx.x * blockDim.x + threadIdx.x;
    if (t >= 4096) return;
    int h = t & 3;
    int k = (t >> 2) & 127;
    int sv = (t >> 9) & 1;
    int rel = (t >> 10) & 1;
    int l = (t >> 11) & 1;
    const float* W;
    const float* att;
    if (rel == 0) { W = sv ? WdstFN : WsrcFN; att = sv ? aDstFN : aSrcFN; }
    else          { W = sv ? WdstNF : WsrcNF; att = sv ? aDstNF : aSrcNF; }
    W += l * DIM * DIM;
    att += l * NH * 32;
    float sum = 0.f;
    #pragma unroll 8
    for (int c = 0; c < 32; c++)
        sum += W[k * DIM + h * 32 + c] * att[h * 32 + c];
    uv[t] = sum;
}

// ---------------- alpha projections: as = x @ v, ad = x @ u ----------------
__global__ void alphaK(const float4* __restrict__ x, const float* __restrict__ vmat,
                       const float* __restrict__ umat, float4* __restrict__ asOut,
                       float4* __restrict__ adOut, int n) {
    __shared__ float sv[512];
    __shared__ float su[512];
    int t = threadIdx.x;
    for (int i = t; i < 512; i += blockDim.x) { sv[i] = vmat[i]; su[i] = umat[i]; }
    __syncthreads();
    int warp = (blockIdx.x * blockDim.x + t) >> 5;
    int lane = t & 31;
    if (warp >= n) return;
    float4 xv = x[warp * 32 + lane];
    float xj[4] = {xv.x, xv.y, xv.z, xv.w};
    float pa[4] = {0, 0, 0, 0}, pd[4] = {0, 0, 0, 0};
    int j0 = lane * 4;
    #pragma unroll
    for (int j = 0; j < 4; j++) {
        #pragma unroll
        for (int h = 0; h < 4; h++) {
            pa[h] += xj[j] * sv[(j0 + j) * 4 + h];
            pd[h] += xj[j] * su[(j0 + j) * 4 + h];
        }
    }
    #pragma unroll
    for (int o = 16; o > 0; o >>= 1) {
        #pragma unroll
        for (int h = 0; h < 4; h++) {
            pa[h] += __shfl_down_sync(0xffffffffu, pa[h], o);
            pd[h] += __shfl_down_sync(0xffffffffu, pd[h], o);
        }
    }
    if (lane == 0) {
        asOut[warp] = make_float4(pa[0], pa[1], pa[2], pa[3]);
        adOut[warp] = make_float4(pd[0], pd[1], pd[2], pd[3]);
    }
}

// ---------------- GEMM: C[M,128] = A[M,128] @ W[128,128], fp16 output ----------------
__global__ void __launch_bounds__(256, 2)
gemmK(const float* __restrict__ A, const float* __restrict__ W,
      __half* __restrict__ C, int M) {
    __shared__ float As[16][132];
    __shared__ float Bs[16][128];
    int t = threadIdx.x;
    int tx = t & 15, ty = t >> 4;
    int rowBase = blockIdx.x * 128;
    float acc[8][8];
    #pragma unroll
    for (int i = 0; i < 8; i++)
        #pragma unroll
        for (int j = 0; j < 8; j++) acc[i][j] = 0.f;

    for (int kk = 0; kk < DIM; kk += 16) {
        #pragma unroll
        for (int i = 0; i < 2; i++) {
            int f = t + i * 256;
            int r = f >> 2;
            int c4 = (f & 3) * 4;
            float4 v = make_float4(0, 0, 0, 0);
            int gr = rowBase + r;
            if (gr < M) v = *(const float4*)(A + gr * DIM + kk + c4);
            As[c4 + 0][r] = v.x;
            As[c4 + 1][r] = v.y;
            As[c4 + 2][r] = v.z;
            As[c4 + 3][r] = v.w;
        }
        #pragma unroll
        for (int i = 0; i < 2; i++) {
            int f = t + i * 256;
            int kr = f >> 5;
            int n4 = (f & 31) * 4;
            *(float4*)(&Bs[kr][n4]) = *(const float4*)(W + (kk + kr) * DIM + n4);
        }
        __syncthreads();
        #pragma unroll
        for (int k = 0; k < 16; k++) {
            float a[8], b[8];
            *(float4*)(a)     = *(float4*)(&As[k][ty * 8]);
            *(float4*)(a + 4) = *(float4*)(&As[k][ty * 8 + 4]);
            *(float4*)(b)     = *(float4*)(&Bs[k][tx * 8]);
            *(float4*)(b + 4) = *(float4*)(&Bs[k][tx * 8 + 4]);
            #pragma unroll
            for (int i = 0; i < 8; i++)
                #pragma unroll
                for (int j = 0; j < 8; j++) acc[i][j] += a[i] * b[j];
        }
        __syncthreads();
    }
    #pragma unroll
    for (int i = 0; i < 8; i++) {
        int gr = rowBase + ty * 8 + i;
        if (gr < M) {
            __half2 h0 = __floats2half2_rn(acc[i][0], acc[i][1]);
            __half2 h1 = __floats2half2_rn(acc[i][2], acc[i][3]);
            __half2 h2 = __floats2half2_rn(acc[i][4], acc[i][5]);
            __half2 h3 = __floats2half2_rn(acc[i][6], acc[i][7]);
            uint4 v;
            v.x = *reinterpret_cast<unsigned*>(&h0);
            v.y = *reinterpret_cast<unsigned*>(&h1);
            v.z = *reinterpret_cast<unsigned*>(&h2);
            v.w = *reinterpret_cast<unsigned*>(&h3);
            *reinterpret_cast<uint4*>(C + gr * DIM + tx * 8) = v;
        }
    }
}

// ---------------- fused softmax-stats + aggregation + bias + ELU ----------------
// warp per dst node. Pass 1: lane-parallel online (m,s) over edges, cache logits
// + src ids in smem. Warp-merge. Pass 2: weighted fp16 gather-accumulate.
__global__ void __launch_bounds__(256)
fusedAggK(const int* __restrict__ off, const int* __restrict__ csrc,
          const float4* __restrict__ as4, const float* __restrict__ as1,
          const float4* __restrict__ ad,
          const __half* __restrict__ hs, const float* __restrict__ bias,
          float4* __restrict__ out, int n) {
    __shared__ float see[8][MAXDEG][4];
    __shared__ int ssrc[8][MAXDEG];
    int w = threadIdx.x >> 5;
    int lane = threadIdx.x & 31;
    int d = blockIdx.x * 8 + w;
    if (d >= n) return;  // warp-uniform

    int beg = off[d], end = off[d + 1];
    int deg = end - beg;
    bool cached = (deg <= MAXDEG);

    float4 adv = ad[d];
    float adh4[4] = {adv.x, adv.y, adv.z, adv.w};
    float m[4] = {-1e30f, -1e30f, -1e30f, -1e30f};
    float s[4] = {0.f, 0.f, 0.f, 0.f};

    // ---- pass 1: per-lane online softmax stats ----
    for (int i = lane; i < deg; i += 32) {
        int src = csrc[beg + i];
        float4 av = as4[src];
        float ev[4] = {av.x + adh4[0], av.y + adh4[1], av.z + adh4[2], av.w + adh4[3]};
        float ee[4];
        #pragma unroll
        for (int h = 0; h < 4; h++) {
            float e = ev[h] > 0.f ? ev[h] : 0.2f * ev[h];
            ee[h] = e;
            if (e > m[h]) {
                s[h] = s[h] * __expf(m[h] - e) + 1.f;
                m[h] = e;
            } else {
                s[h] += __expf(e - m[h]);
            }
        }
        if (cached) {
            ssrc[w][i] = src;
            *(float4*)(&see[w][i][0]) = make_float4(ee[0], ee[1], ee[2], ee[3]);
        }
    }
    // ---- warp merge of (m, s) ----
    #pragma unroll
    for (int o = 16; o > 0; o >>= 1) {
        #pragma unroll
        for (int h = 0; h < 4; h++) {
            float om = __shfl_xor_sync(0xffffffffu, m[h], o);
            float os = __shfl_xor_sync(0xffffffffu, s[h], o);
            float nm = fmaxf(m[h], om);
            s[h] = s[h] * __expf(m[h] - nm) + os * __expf(om - nm);
            m[h] = nm;
        }
    }
    __syncwarp();

    int h = lane >> 3;
    float mh = m[h];
    float rh = 1.f / (s[h] + 1e-16f);
    float adh = adh4[h];

    // ---- pass 2: weighted aggregation ----
    float4 acc = make_float4(0.f, 0.f, 0.f, 0.f);
    for (int e = 0; e < deg; e++) {
        int src;
        float ee;
        if (cached) {
            src = ssrc[w][e];
            ee = see[w][e][h];
        } else {
            src = csrc[beg + e];
            float a = __ldg(&as1[src * 4 + h]);
            float ev = a + adh;
            ee = ev > 0.f ? ev : 0.2f * ev;
        }
        float wgt = __expf(ee - mh) * rh;
        const __half2* hp = reinterpret_cast<const __half2*>(hs + src * DIM) + lane * 2;
        __half2 p0 = hp[0], p1 = hp[1];
        float2 f0 = __half22float2(p0);
        float2 f1 = __half22float2(p1);
        acc.x += wgt * f0.x;
        acc.y += wgt * f0.y;
        acc.z += wgt * f1.x;
        acc.w += wgt * f1.y;
    }
    float4 b = *(const float4*)(bias + lane * 4);
    acc.x += b.x; acc.y += b.y; acc.z += b.z; acc.w += b.w;
    acc.x = acc.x > 0.f ? acc.x : expm1f(acc.x);
    acc.y = acc.y > 0.f ? acc.y : expm1f(acc.y);
    acc.z = acc.z > 0.f ? acc.z : expm1f(acc.z);
    acc.w = acc.w > 0.f ? acc.w : expm1f(acc.w);
    out[d * 32 + lane] = acc;
}

// ---------------- driver ----------------
extern "C" void kernel_launch(void* const* d_in, const int* in_sizes, int n_in,
                              void* d_out, int out_size) {
    const float* x_food  = (const float*)d_in[0];
    const float* x_nut   = (const float*)d_in[1];
    const float* WsrcFN  = (const float*)d_in[2];
    const float* WdstFN  = (const float*)d_in[3];
    const float* aSrcFN  = (const float*)d_in[4];
    const float* aDstFN  = (const float*)d_in[5];
    const float* biasFN  = (const float*)d_in[6];
    const float* WsrcNF  = (const float*)d_in[7];
    const float* WdstNF  = (const float*)d_in[8];
    const float* aSrcNF  = (const float*)d_in[9];
    const float* aDstNF  = (const float*)d_in[10];
    const float* biasNF  = (const float*)d_in[11];
    const int*   ei_fn   = (const int*)d_in[12];
    const int*   ei_nf   = (const int*)d_in[13];
    float* out = (float*)d_out;

    int NF = in_sizes[0] / DIM;
    int NN = in_sizes[1] / DIM;
    int E  = in_sizes[12] / 2;

    __half* hs;
    float *hfood, *hnut, *asA, *adA, *asB, *adB, *uv;
    int *deg, *cur, *offA, *offB, *srcA, *srcB;
    cudaGetSymbolAddress((void**)&hs, g_hs);
    cudaGetSymbolAddress((void**)&hfood, g_hfood);
    cudaGetSymbolAddress((void**)&hnut, g_hnut);
    cudaGetSymbolAddress((void**)&asA, g_asA);
    cudaGetSymbolAddress((void**)&adA, g_adA);
    cudaGetSymbolAddress((void**)&asB, g_asB);
    cudaGetSymbolAddress((void**)&adB, g_adB);
    cudaGetSymbolAddress((void**)&uv, g_uv);
    cudaGetSymbolAddress((void**)&deg, g_deg);
    cudaGetSymbolAddress((void**)&cur, g_cur);
    cudaGetSymbolAddress((void**)&offA, g_offA);
    cudaGetSymbolAddress((void**)&offB, g_offB);
    cudaGetSymbolAddress((void**)&srcA, g_srcA);
    cudaGetSymbolAddress((void**)&srcB, g_srcB);

    int* degA = deg;
    int* degB = deg + MAXN;
    int* curA = cur;
    int* curB = cur + MAXN;

    int warpBlk_NN = (NN + 7) / 8;
    int warpBlk_NF = (NF + 7) / 8;
    int gemmBlk_NF = (NF + 127) / 128;
    int gemmBlk_NN = (NN + 127) / 128;

    // merged CSR build for both relations
    cudaMemsetAsync(deg, 0, 2 * MAXN * sizeof(int));
    histK2<<<1024, 256>>>(ei_fn + E, ei_nf + E, degA, degB, E);
    scan2K<<<2, 1024>>>(degA, offA, curA, NN, degB, offB, curB, NF);
    fillK2<<<1024, 256>>>(ei_fn, ei_nf, curA, curB, srcA, srcB, E);
    sortK2<<<(NN + NF + 255) / 256, 256>>>(offA, srcA, NN, offB, srcB, NF);

    uvK<<<16, 256>>>(WsrcFN, WdstFN, aSrcFN, aDstFN, WsrcNF, WdstNF, aSrcNF, aDstNF, uv);

    for (int l = 0; l < 2; l++) {
        const float* inF = l ? hfood : x_food;
        const float* inN = l ? hnut : x_nut;
        float* outF = l ? out : hfood;
        float* outN = l ? out + (size_t)NF * DIM : hnut;
        const float* v_fn = uv + l * 2048 + 0 * 1024 + 0 * 512;
        const float* u_fn = uv + l * 2048 + 0 * 1024 + 1 * 512;
        const float* v_nf = uv + l * 2048 + 1 * 1024 + 0 * 512;
        const float* u_nf = uv + l * 2048 + 1 * 1024 + 1 * 512;

        alphaK<<<warpBlk_NF, 256>>>((const float4*)inF, v_fn, u_nf,
                                    (float4*)asA, (float4*)adB, NF);
        alphaK<<<warpBlk_NN, 256>>>((const float4*)inN, v_nf, u_fn,
                                    (float4*)asB, (float4*)adA, NN);

        // relation fn: food -> nutrient
        gemmK<<<gemmBlk_NF, 256>>>(inF, WsrcFN + l * DIM * DIM, hs, NF);
        fusedAggK<<<warpBlk_NN, 256>>>(offA, srcA, (const float4*)asA, asA,
                                       (const float4*)adA, hs, biasFN + l * DIM,
                                       (float4*)outN, NN);

        // relation nf: nutrient -> food
        gemmK<<<gemmBlk_NN, 256>>>(inN, WsrcNF + l * DIM * DIM, hs, NN);
        fusedAggK<<<warpBlk_NF, 256>>>(offB, srcB, (const float4*)asB, asB,
                                       (const float4*)adB, hs, biasNF + l * DIM,
                                       (float4*)outF, NF);
    }
}

// round 3
// speedup vs baseline: 1.1923x; 1.0357x over previous
#include <cuda_runtime.h>
#include <cuda_fp16.h>
#include <mma.h>
#include <math.h>
#include <limits.h>

using namespace nvcuda;

#define DIM 128
#define NH 4
#define MAXN 50048
#define MAXE 800032
#define MAXDEG 96

// ---------------- scratch (static device globals; no allocation) ----------------
__device__ __half g_hs[MAXN * DIM];     // hs = x_src @ Wsrc (fp16 messages)
__device__ __half g_Wh[4 * DIM * DIM];  // fp16 Wsrc: [rel][l][128*128]
__device__ float g_hfood[MAXN * DIM];   // layer-1 food output
__device__ float g_hnut[MAXN * DIM];    // layer-1 nut output
__device__ float g_asA[MAXN * NH];
__device__ float g_adA[MAXN * NH];
__device__ float g_asB[MAXN * NH];
__device__ float g_adB[MAXN * NH];
__device__ float g_uv[4096];            // folded attention vectors [l][rel][s/d][k][h]
__device__ int   g_deg[2 * MAXN];
__device__ int   g_cur[2 * MAXN];
__device__ int   g_offA[MAXN + 1];
__device__ int   g_offB[MAXN + 1];
__device__ int   g_srcA[MAXE];
__device__ int   g_srcB[MAXE];

// ---------------- CSR build (both relations in one pass) ----------------
__global__ void histK2(const int* __restrict__ dstA, const int* __restrict__ dstB,
                       int* __restrict__ degA, int* __restrict__ degB, int E) {
    int i = blockIdx.x * blockDim.x + threadIdx.x;
    int stride = gridDim.x * blockDim.x;
    for (; i < 2 * E; i += stride) {
        if (i < E) atomicAdd(&degA[dstA[i]], 1);
        else       atomicAdd(&degB[dstB[i - E]], 1);
    }
}

__global__ void scan2K(const int* __restrict__ degA, int* __restrict__ offA, int* __restrict__ curA, int nA,
                       const int* __restrict__ degB, int* __restrict__ offB, int* __restrict__ curB, int nB) {
    __shared__ int sh[1024];
    const int* deg = blockIdx.x ? degB : degA;
    int* off = blockIdx.x ? offB : offA;
    int* cur = blockIdx.x ? curB : curA;
    int n = blockIdx.x ? nB : nA;
    int t = threadIdx.x;
    int chunk = (n + 1023) / 1024;
    int start = t * chunk;
    int mySum = 0;
    for (int i = 0; i < chunk; i++) {
        int idx = start + i;
        if (idx < n) mySum += deg[idx];
    }
    sh[t] = mySum;
    __syncthreads();
    for (int d = 1; d < 1024; d <<= 1) {
        int v = 0;
        if (t >= d) v = sh[t - d];
        __syncthreads();
        if (t >= d) sh[t] += v;
        __syncthreads();
    }
    int run = sh[t] - mySum;
    for (int i = 0; i < chunk; i++) {
        int idx = start + i;
        if (idx < n) { off[idx] = run; cur[idx] = run; run += deg[idx]; }
    }
    if (t == 0) off[n] = sh[1023];
}

__global__ void fillK2(const int* __restrict__ eiA, const int* __restrict__ eiB,
                       int* __restrict__ curA, int* __restrict__ curB,
                       int* __restrict__ srcA, int* __restrict__ srcB, int E) {
    int i = blockIdx.x * blockDim.x + threadIdx.x;
    int stride = gridDim.x * blockDim.x;
    for (; i < 2 * E; i += stride) {
        if (i < E) {
            int pos = atomicAdd(&curA[eiA[E + i]], 1);
            srcA[pos] = eiA[i];
        } else {
            int j = i - E;
            int pos = atomicAdd(&curB[eiB[E + j]], 1);
            srcB[pos] = eiB[j];
        }
    }
}

// ---------------- warp-per-bucket bitonic sort (deterministic order) ----------------
__global__ void __launch_bounds__(256)
sortWarpK(const int* __restrict__ offA, int* __restrict__ srcA, int nA,
          const int* __restrict__ offB, int* __restrict__ srcB, int nB) {
    int w = (blockIdx.x * blockDim.x + threadIdx.x) >> 5;
    int lane = threadIdx.x & 31;
    const int* off; int* csrc; int d = w;
    if (w < nA) { off = offA; csrc = srcA; }
    else if (w < nA + nB) { off = offB; csrc = srcB; d = w - nA; }
    else return;
    int beg = off[d];
    int deg = off[d + 1] - beg;
    if (deg <= 1) return;
    if (deg <= 64) {
        int v0 = (lane < deg) ? csrc[beg + lane] : INT_MAX;
        int v1 = (32 + lane < deg) ? csrc[beg + 32 + lane] : INT_MAX;
        #pragma unroll
        for (int size = 2; size <= 64; size <<= 1) {
            #pragma unroll
            for (int stride = size >> 1; stride > 0; stride >>= 1) {
                if (stride == 32) {
                    int lo = min(v0, v1), hi = max(v0, v1);
                    v0 = lo; v1 = hi;
                } else {
                    int p0 = __shfl_xor_sync(0xffffffffu, v0, stride);
                    int p1 = __shfl_xor_sync(0xffffffffu, v1, stride);
                    bool up0, up1;
                    if (size == 64)      { up0 = true; up1 = true; }
                    else if (size == 32) { up0 = true; up1 = false; }
                    else { up0 = ((lane & size) == 0); up1 = up0; }
                    bool lower = ((lane & stride) == 0);
                    v0 = (lower == up0) ? min(v0, p0) : max(v0, p0);
                    v1 = (lower == up1) ? min(v1, p1) : max(v1, p1);
                }
            }
        }
        if (lane < deg) csrc[beg + lane] = v0;
        if (32 + lane < deg) csrc[beg + 32 + lane] = v1;
    } else if (lane == 0) {
        int end = beg + deg;
        for (int i = beg + 1; i < end; i++) {
            int key = csrc[i];
            int j = i - 1;
            while (j >= beg && csrc[j] > key) { csrc[j + 1] = csrc[j]; j--; }
            csrc[j + 1] = key;
        }
    }
}

// ---------------- folded attention vectors ----------------
__global__ void uvK(const float* __restrict__ WsrcFN, const float* __restrict__ WdstFN,
                    const float* __restrict__ aSrcFN, const float* __restrict__ aDstFN,
                    const float* __restrict__ WsrcNF, const float* __restrict__ WdstNF,
                    const float* __restrict__ aSrcNF, const float* __restrict__ aDstNF,
                    float* __restrict__ uv) {
    int t = blockIdx.x * blockDim.x + threadIdx.x;
    if (t >= 4096) return;
    int h = t & 3;
    int k = (t >> 2) & 127;
    int sv = (t >> 9) & 1;
    int rel = (t >> 10) & 1;
    int l = (t >> 11) & 1;
    const float* W;
    const float* att;
    if (rel == 0) { W = sv ? WdstFN : WsrcFN; att = sv ? aDstFN : aSrcFN; }
    else          { W = sv ? WdstNF : WsrcNF; att = sv ? aDstNF : aSrcNF; }
    W += l * DIM * DIM;
    att += l * NH * 32;
    float sum = 0.f;
    #pragma unroll 8
    for (int c = 0; c < 32; c++)
        sum += W[k * DIM + h * 32 + c] * att[h * 32 + c];
    uv[t] = sum;
}

// ---------------- fp16 weight conversion ----------------
__global__ void convWK(const float* __restrict__ WsrcFN, const float* __restrict__ WsrcNF,
                       __half* __restrict__ Wh) {
    int i = blockIdx.x * blockDim.x + threadIdx.x;
    if (i >= 4 * DIM * DIM) return;
    int rel = i >> 15;
    int rest = i & 32767;
    const float* W = rel ? WsrcNF : WsrcFN;
    Wh[i] = __float2half(W[rest]);
}

// ---------------- alpha projections: as = x @ v, ad = x @ u ----------------
__global__ void alphaK(const float4* __restrict__ x, const float* __restrict__ vmat,
                       const float* __restrict__ umat, float4* __restrict__ asOut,
                       float4* __restrict__ adOut, int n) {
    __shared__ float sv[512];
    __shared__ float su[512];
    int t = threadIdx.x;
    for (int i = t; i < 512; i += blockDim.x) { sv[i] = vmat[i]; su[i] = umat[i]; }
    __syncthreads();
    int warp = (blockIdx.x * blockDim.x + t) >> 5;
    int lane = t & 31;
    if (warp >= n) return;
    float4 xv = x[warp * 32 + lane];
    float xj[4] = {xv.x, xv.y, xv.z, xv.w};
    float pa[4] = {0, 0, 0, 0}, pd[4] = {0, 0, 0, 0};
    int j0 = lane * 4;
    #pragma unroll
    for (int j = 0; j < 4; j++) {
        #pragma unroll
        for (int h = 0; h < 4; h++) {
            pa[h] += xj[j] * sv[(j0 + j) * 4 + h];
            pd[h] += xj[j] * su[(j0 + j) * 4 + h];
        }
    }
    #pragma unroll
    for (int o = 16; o > 0; o >>= 1) {
        #pragma unroll
        for (int h = 0; h < 4; h++) {
            pa[h] += __shfl_down_sync(0xffffffffu, pa[h], o);
            pd[h] += __shfl_down_sync(0xffffffffu, pd[h], o);
        }
    }
    if (lane == 0) {
        asOut[warp] = make_float4(pa[0], pa[1], pa[2], pa[3]);
        adOut[warp] = make_float4(pd[0], pd[1], pd[2], pd[3]);
    }
}

// ---------------- tensor-core GEMM: C[M,128] = A[M,128] @ W[128,128] ----------------
// A fp32 -> fp16 converted on smem staging, W pre-converted fp16, wmma HMMA, fp32 accum.
// Block: 256 threads (8 warps), tile 64 rows x 128 cols. Warp grid 4x2, warp = 16x64.
__global__ void __launch_bounds__(256)
gemmTC(const float* __restrict__ A, const __half* __restrict__ Wh,
       __half* __restrict__ C, int M) {
    __shared__ union {
        __half a[64 * 136];
        float c[64 * 132];
    } sm;
    int t = threadIdx.x;
    int rowBase = blockIdx.x * 64;

    // stage A tile (64x128 fp32 -> fp16 smem, ldm 136)
    {
        int r = t >> 2;              // 0..63
        int c0 = (t & 3) * 32;       // 0,32,64,96
        int gr = rowBase + r;
        const float4* src = (const float4*)(A + (size_t)gr * DIM + c0);
        __half* dst = &sm.a[r * 136 + c0];
        if (gr < M) {
            #pragma unroll
            for (int i = 0; i < 8; i++) {
                float4 v = src[i];
                __half2 h01 = __floats2half2_rn(v.x, v.y);
                __half2 h23 = __floats2half2_rn(v.z, v.w);
                *(__half2*)(dst + i * 4)     = h01;
                *(__half2*)(dst + i * 4 + 2) = h23;
            }
        } else {
            #pragma unroll
            for (int i = 0; i < 8; i++) {
                *(__half2*)(dst + i * 4)     = __half2half2(__float2half(0.f));
                *(__half2*)(dst + i * 4 + 2) = __half2half2(__float2half(0.f));
            }
        }
    }
    __syncthreads();

    int warpId = t >> 5;
    int wr = warpId & 3;   // row tile 0..3 (16 rows each)
    int wc = warpId >> 2;  // col half 0..1 (64 cols each)

    wmma::fragment<wmma::accumulator, 16, 16, 16, float> cf[4];
    #pragma unroll
    for (int j = 0; j < 4; j++) wmma::fill_fragment(cf[j], 0.f);

    #pragma unroll
    for (int k0 = 0; k0 < 8; k0++) {
        wmma::fragment<wmma::matrix_a, 16, 16, 16, __half, wmma::row_major> af;
        wmma::load_matrix_sync(af, &sm.a[(wr * 16) * 136 + k0 * 16], 136);
        #pragma unroll
        for (int j = 0; j < 4; j++) {
            wmma::fragment<wmma::matrix_b, 16, 16, 16, __half, wmma::row_major> bf;
            wmma::load_matrix_sync(bf, Wh + (k0 * 16) * DIM + wc * 64 + j * 16, DIM);
            wmma::mma_sync(cf[j], af, bf, cf[j]);
        }
    }
    __syncthreads();  // done reading sm.a

    #pragma unroll
    for (int j = 0; j < 4; j++)
        wmma::store_matrix_sync(&sm.c[(wr * 16) * 132 + wc * 64 + j * 16], cf[j], 132,
                                wmma::mem_row_major);
    __syncthreads();

    // write out fp16
    {
        int r = t >> 2;
        int c0 = (t & 3) * 32;
        int gr = rowBase + r;
        if (gr < M) {
            const float* src = &sm.c[r * 132 + c0];
            __half2* dst = (__half2*)(C + (size_t)gr * DIM + c0);
            #pragma unroll
            for (int i = 0; i < 16; i++)
                dst[i] = __floats2half2_rn(src[2 * i], src[2 * i + 1]);
        }
    }
}

// ---------------- fused softmax-stats + aggregation + bias + ELU ----------------
__global__ void __launch_bounds__(256)
fusedAggK(const int* __restrict__ off, const int* __restrict__ csrc,
          const float4* __restrict__ as4, const float* __restrict__ as1,
          const float4* __restrict__ ad,
          const __half* __restrict__ hs, const float* __restrict__ bias,
          float4* __restrict__ out, int n) {
    __shared__ float see[8][MAXDEG][4];
    __shared__ int ssrc[8][MAXDEG];
    int w = threadIdx.x >> 5;
    int lane = threadIdx.x & 31;
    int d = blockIdx.x * 8 + w;
    if (d >= n) return;

    int beg = off[d], end = off[d + 1];
    int deg = end - beg;
    bool cached = (deg <= MAXDEG);

    float4 adv = ad[d];
    float adh4[4] = {adv.x, adv.y, adv.z, adv.w};
    float m[4] = {-1e30f, -1e30f, -1e30f, -1e30f};
    float s[4] = {0.f, 0.f, 0.f, 0.f};

    for (int i = lane; i < deg; i += 32) {
        int src = csrc[beg + i];
        float4 av = as4[src];
        float ev[4] = {av.x + adh4[0], av.y + adh4[1], av.z + adh4[2], av.w + adh4[3]};
        float ee[4];
        #pragma unroll
        for (int h = 0; h < 4; h++) {
            float e = ev[h] > 0.f ? ev[h] : 0.2f * ev[h];
            ee[h] = e;
            if (e > m[h]) {
                s[h] = s[h] * __expf(m[h] - e) + 1.f;
                m[h] = e;
            } else {
                s[h] += __expf(e - m[h]);
            }
        }
        if (cached) {
            ssrc[w][i] = src;
            *(float4*)(&see[w][i][0]) = make_float4(ee[0], ee[1], ee[2], ee[3]);
        }
    }
    #pragma unroll
    for (int o = 16; o > 0; o >>= 1) {
        #pragma unroll
        for (int h = 0; h < 4; h++) {
            float om = __shfl_xor_sync(0xffffffffu, m[h], o);
            float os = __shfl_xor_sync(0xffffffffu, s[h], o);
            float nm = fmaxf(m[h], om);
            s[h] = s[h] * __expf(m[h] - nm) + os * __expf(om - nm);
            m[h] = nm;
        }
    }
    __syncwarp();

    int h = lane >> 3;
    float mh = m[h];
    float rh = 1.f / (s[h] + 1e-16f);
    float adh = adh4[h];

    float4 acc = make_float4(0.f, 0.f, 0.f, 0.f);
    for (int e = 0; e < deg; e++) {
        int src;
        float ee;
        if (cached) {
            src = ssrc[w][e];
            ee = see[w][e][h];
        } else {
            src = csrc[beg + e];
            float a = __ldg(&as1[src * 4 + h]);
            float ev = a + adh;
            ee = ev > 0.f ? ev : 0.2f * ev;
        }
        float wgt = __expf(ee - mh) * rh;
        const __half2* hp = reinterpret_cast<const __half2*>(hs + src * DIM) + lane * 2;
        __half2 p0 = hp[0], p1 = hp[1];
        float2 f0 = __half22float2(p0);
        float2 f1 = __half22float2(p1);
        acc.x += wgt * f0.x;
        acc.y += wgt * f0.y;
        acc.z += wgt * f1.x;
        acc.w += wgt * f1.y;
    }
    float4 b = *(const float4*)(bias + lane * 4);
    acc.x += b.x; acc.y += b.y; acc.z += b.z; acc.w += b.w;
    acc.x = acc.x > 0.f ? acc.x : expm1f(acc.x);
    acc.y = acc.y > 0.f ? acc.y : expm1f(acc.y);
    acc.z = acc.z > 0.f ? acc.z : expm1f(acc.z);
    acc.w = acc.w > 0.f ? acc.w : expm1f(acc.w);
    out[d * 32 + lane] = acc;
}

// ---------------- driver ----------------
extern "C" void kernel_launch(void* const* d_in, const int* in_sizes, int n_in,
                              void* d_out, int out_size) {
    const float* x_food  = (const float*)d_in[0];
    const float* x_nut   = (const float*)d_in[1];
    const float* WsrcFN  = (const float*)d_in[2];
    const float* WdstFN  = (const float*)d_in[3];
    const float* aSrcFN  = (const float*)d_in[4];
    const float* aDstFN  = (const float*)d_in[5];
    const float* biasFN  = (const float*)d_in[6];
    const float* WsrcNF  = (const float*)d_in[7];
    const float* WdstNF  = (const float*)d_in[8];
    const float* aSrcNF  = (const float*)d_in[9];
    const float* aDstNF  = (const float*)d_in[10];
    const float* biasNF  = (const float*)d_in[11];
    const int*   ei_fn   = (const int*)d_in[12];
    const int*   ei_nf   = (const int*)d_in[13];
    float* out = (float*)d_out;

    int NF = in_sizes[0] / DIM;
    int NN = in_sizes[1] / DIM;
    int E  = in_sizes[12] / 2;

    __half *hs, *Wh;
    float *hfood, *hnut, *asA, *adA, *asB, *adB, *uv;
    int *deg, *cur, *offA, *offB, *srcA, *srcB;
    cudaGetSymbolAddress((void**)&hs, g_hs);
    cudaGetSymbolAddress((void**)&Wh, g_Wh);
    cudaGetSymbolAddress((void**)&hfood, g_hfood);
    cudaGetSymbolAddress((void**)&hnut, g_hnut);
    cudaGetSymbolAddress((void**)&asA, g_asA);
    cudaGetSymbolAddress((void**)&adA, g_adA);
    cudaGetSymbolAddress((void**)&asB, g_asB);
    cudaGetSymbolAddress((void**)&adB, g_adB);
    cudaGetSymbolAddress((void**)&uv, g_uv);
    cudaGetSymbolAddress((void**)&deg, g_deg);
    cudaGetSymbolAddress((void**)&cur, g_cur);
    cudaGetSymbolAddress((void**)&offA, g_offA);
    cudaGetSymbolAddress((void**)&offB, g_offB);
    cudaGetSymbolAddress((void**)&srcA, g_srcA);
    cudaGetSymbolAddress((void**)&srcB, g_srcB);

    int* degA = deg;
    int* degB = deg + MAXN;
    int* curA = cur;
    int* curB = cur + MAXN;

    int warpBlk_NN = (NN + 7) / 8;
    int warpBlk_NF = (NF + 7) / 8;
    int gemmBlk_NF = (NF + 63) / 64;
    int gemmBlk_NN = (NN + 63) / 64;

    // merged CSR build for both relations
    cudaMemsetAsync(deg, 0, 2 * MAXN * sizeof(int));
    histK2<<<1024, 256>>>(ei_fn + E, ei_nf + E, degA, degB, E);
    scan2K<<<2, 1024>>>(degA, offA, curA, NN, degB, offB, curB, NF);
    fillK2<<<1024, 256>>>(ei_fn, ei_nf, curA, curB, srcA, srcB, E);
    sortWarpK<<<(NN + NF + 7) / 8, 256>>>(offA, srcA, NN, offB, srcB, NF);

    uvK<<<16, 256>>>(WsrcFN, WdstFN, aSrcFN, aDstFN, WsrcNF, WdstNF, aSrcNF, aDstNF, uv);
    convWK<<<(4 * DIM * DIM + 255) / 256, 256>>>(WsrcFN, WsrcNF, Wh);

    for (int l = 0; l < 2; l++) {
        const float* inF = l ? hfood : x_food;
        const float* inN = l ? hnut : x_nut;
        float* outF = l ? out : hfood;
        float* outN = l ? out + (size_t)NF * DIM : hnut;
        const float* v_fn = uv + l * 2048 + 0 * 1024 + 0 * 512;
        const float* u_fn = uv + l * 2048 + 0 * 1024 + 1 * 512;
        const float* v_nf = uv + l * 2048 + 1 * 1024 + 0 * 512;
        const float* u_nf = uv + l * 2048 + 1 * 1024 + 1 * 512;
        const __half* Wh_fn = Wh + (0 * 2 + l) * DIM * DIM;
        const __half* Wh_nf = Wh + (1 * 2 + l) * DIM * DIM;

        alphaK<<<warpBlk_NF, 256>>>((const float4*)inF, v_fn, u_nf,
                                    (float4*)asA, (float4*)adB, NF);
        alphaK<<<warpBlk_NN, 256>>>((const float4*)inN, v_nf, u_fn,
                                    (float4*)asB, (float4*)adA, NN);

        // relation fn: food -> nutrient
        gemmTC<<<gemmBlk_NF, 256>>>(inF, Wh_fn, hs, NF);
        fusedAggK<<<warpBlk_NN, 256>>>(offA, srcA, (const float4*)asA, asA,
                                       (const float4*)adA, hs, biasFN + l * DIM,
                                       (float4*)outN, NN);

        // relation nf: nutrient -> food
        gemmTC<<<gemmBlk_NN, 256>>>(inN, Wh_nf, hs, NN);
        fusedAggK<<<warpBlk_NF, 256>>>(offB, srcB, (const float4*)asB, asB,
                                       (const float4*)adB, hs, biasNF + l * DIM,
                                       (float4*)outF, NF);
    }
}

// round 4
// speedup vs baseline: 1.4254x; 1.1955x over previous
#include <cuda_runtime.h>
#include <cuda_fp16.h>
#include <mma.h>
#include <math.h>
#include <limits.h>

using namespace nvcuda;

#define DIM 128
#define NH 4
#define MAXN 50048
#define MAXE 800032
#define MAXDEG 96

// ---------------- scratch (static device globals; no allocation) ----------------
__device__ __half g_hsA[MAXN * DIM];    // fn-relation messages
__device__ __half g_hsB[MAXN * DIM];    // nf-relation messages
__device__ __half g_Wh[4 * DIM * DIM];  // fp16 Wsrc: [rel][l][128*128]
__device__ float g_hfood[MAXN * DIM];
__device__ float g_hnut[MAXN * DIM];
__device__ float g_asA[MAXN * NH];
__device__ float g_adA[MAXN * NH];
__device__ float g_asB[MAXN * NH];
__device__ float g_adB[MAXN * NH];
__device__ float g_uv[4096];
__device__ int   g_deg[2 * MAXN];       // zero-initialized; re-zeroed by sortZK epilogue
__device__ int   g_cur[2 * MAXN];
__device__ int   g_offA[MAXN + 1];
__device__ int   g_offB[MAXN + 1];
__device__ int   g_srcA[MAXE];
__device__ int   g_srcB[MAXE];

// ---------------- CSR build (per relation, stream-parallel) ----------------
__global__ void histK(const int* __restrict__ dst, int* __restrict__ deg, int E) {
    int i = blockIdx.x * blockDim.x + threadIdx.x;
    int stride = gridDim.x * blockDim.x;
    for (; i < E; i += stride) atomicAdd(&deg[dst[i]], 1);
}

__global__ void scanK(const int* __restrict__ deg, int* __restrict__ off,
                      int* __restrict__ cur, int n) {
    __shared__ int sh[1024];
    int t = threadIdx.x;
    int chunk = (n + 1023) / 1024;
    int start = t * chunk;
    int mySum = 0;
    for (int i = 0; i < chunk; i++) {
        int idx = start + i;
        if (idx < n) mySum += deg[idx];
    }
    sh[t] = mySum;
    __syncthreads();
    for (int d = 1; d < 1024; d <<= 1) {
        int v = 0;
        if (t >= d) v = sh[t - d];
        __syncthreads();
        if (t >= d) sh[t] += v;
        __syncthreads();
    }
    int run = sh[t] - mySum;
    for (int i = 0; i < chunk; i++) {
        int idx = start + i;
        if (idx < n) { off[idx] = run; cur[idx] = run; run += deg[idx]; }
    }
    if (t == 0) off[n] = sh[1023];
}

__global__ void fillK(const int* __restrict__ ei, int* __restrict__ cur,
                      int* __restrict__ csrc, int E) {
    int i = blockIdx.x * blockDim.x + threadIdx.x;
    int stride = gridDim.x * blockDim.x;
    for (; i < E; i += stride) {
        int pos = atomicAdd(&cur[ei[E + i]], 1);
        csrc[pos] = ei[i];
    }
}

// warp-per-bucket bitonic sort + epilogue zeroing of deg for next graph replay
__global__ void __launch_bounds__(256)
sortZK(const int* __restrict__ off, int* __restrict__ csrc, int n,
       int* __restrict__ deg) {
    // zero deg (not read by this kernel; consumed by NEXT replay's histK)
    for (int i = blockIdx.x * blockDim.x + threadIdx.x; i < n;
         i += gridDim.x * blockDim.x) deg[i] = 0;

    int w = (blockIdx.x * blockDim.x + threadIdx.x) >> 5;
    int lane = threadIdx.x & 31;
    if (w >= n) return;
    int beg = off[w];
    int cnt = off[w + 1] - beg;
    if (cnt <= 1) return;
    if (cnt <= 64) {
        int v0 = (lane < cnt) ? csrc[beg + lane] : INT_MAX;
        int v1 = (32 + lane < cnt) ? csrc[beg + 32 + lane] : INT_MAX;
        #pragma unroll
        for (int size = 2; size <= 64; size <<= 1) {
            #pragma unroll
            for (int stride = size >> 1; stride > 0; stride >>= 1) {
                if (stride == 32) {
                    int lo = min(v0, v1), hi = max(v0, v1);
                    v0 = lo; v1 = hi;
                } else {
                    int p0 = __shfl_xor_sync(0xffffffffu, v0, stride);
                    int p1 = __shfl_xor_sync(0xffffffffu, v1, stride);
                    bool up0, up1;
                    if (size == 64)      { up0 = true; up1 = true; }
                    else if (size == 32) { up0 = true; up1 = false; }
                    else { up0 = ((lane & size) == 0); up1 = up0; }
                    bool lower = ((lane & stride) == 0);
                    v0 = (lower == up0) ? min(v0, p0) : max(v0, p0);
                    v1 = (lower == up1) ? min(v1, p1) : max(v1, p1);
                }
            }
        }
        if (lane < cnt) csrc[beg + lane] = v0;
        if (32 + lane < cnt) csrc[beg + 32 + lane] = v1;
    } else if (lane == 0) {
        int end = beg + cnt;
        for (int i = beg + 1; i < end; i++) {
            int key = csrc[i];
            int j = i - 1;
            while (j >= beg && csrc[j] > key) { csrc[j + 1] = csrc[j]; j--; }
            csrc[j + 1] = key;
        }
    }
}

// ---------------- folded attention vectors ----------------
__global__ void uvK(const float* __restrict__ WsrcFN, const float* __restrict__ WdstFN,
                    const float* __restrict__ aSrcFN, const float* __restrict__ aDstFN,
                    const float* __restrict__ WsrcNF, const float* __restrict__ WdstNF,
                    const float* __restrict__ aSrcNF, const float* __restrict__ aDstNF,
                    float* __restrict__ uv) {
    int t = blockIdx.x * blockDim.x + threadIdx.x;
    if (t >= 4096) return;
    int h = t & 3;
    int k = (t >> 2) & 127;
    int sv = (t >> 9) & 1;
    int rel = (t >> 10) & 1;
    int l = (t >> 11) & 1;
    const float* W;
    const float* att;
    if (rel == 0) { W = sv ? WdstFN : WsrcFN; att = sv ? aDstFN : aSrcFN; }
    else          { W = sv ? WdstNF : WsrcNF; att = sv ? aDstNF : aSrcNF; }
    W += l * DIM * DIM;
    att += l * NH * 32;
    float sum = 0.f;
    #pragma unroll 8
    for (int c = 0; c < 32; c++)
        sum += W[k * DIM + h * 32 + c] * att[h * 32 + c];
    uv[t] = sum;
}

// ---------------- fp16 weight conversion ----------------
__global__ void convWK(const float* __restrict__ WsrcFN, const float* __restrict__ WsrcNF,
                       __half* __restrict__ Wh) {
    int i = blockIdx.x * blockDim.x + threadIdx.x;
    if (i >= 4 * DIM * DIM) return;
    int rel = i >> 15;
    int rest = i & 32767;
    const float* W = rel ? WsrcNF : WsrcFN;
    Wh[i] = __float2half(W[rest]);
}

// ---------------- alpha projections: as = x @ v, ad = x @ u ----------------
__global__ void alphaK(const float4* __restrict__ x, const float* __restrict__ vmat,
                       const float* __restrict__ umat, float4* __restrict__ asOut,
                       float4* __restrict__ adOut, int n) {
    __shared__ float sv[512];
    __shared__ float su[512];
    int t = threadIdx.x;
    for (int i = t; i < 512; i += blockDim.x) { sv[i] = vmat[i]; su[i] = umat[i]; }
    __syncthreads();
    int warp = (blockIdx.x * blockDim.x + t) >> 5;
    int lane = t & 31;
    if (warp >= n) return;
    float4 xv = x[warp * 32 + lane];
    float xj[4] = {xv.x, xv.y, xv.z, xv.w};
    float pa[4] = {0, 0, 0, 0}, pd[4] = {0, 0, 0, 0};
    int j0 = lane * 4;
    #pragma unroll
    for (int j = 0; j < 4; j++) {
        #pragma unroll
        for (int h = 0; h < 4; h++) {
            pa[h] += xj[j] * sv[(j0 + j) * 4 + h];
            pd[h] += xj[j] * su[(j0 + j) * 4 + h];
        }
    }
    #pragma unroll
    for (int o = 16; o > 0; o >>= 1) {
        #pragma unroll
        for (int h = 0; h < 4; h++) {
            pa[h] += __shfl_down_sync(0xffffffffu, pa[h], o);
            pd[h] += __shfl_down_sync(0xffffffffu, pd[h], o);
        }
    }
    if (lane == 0) {
        asOut[warp] = make_float4(pa[0], pa[1], pa[2], pa[3]);
        adOut[warp] = make_float4(pd[0], pd[1], pd[2], pd[3]);
    }
}

// ---------------- tensor-core GEMM: C[M,128] = A[M,128] @ W[128,128] ----------------
__global__ void __launch_bounds__(256)
gemmTC(const float* __restrict__ A, const __half* __restrict__ Wh,
       __half* __restrict__ C, int M) {
    __shared__ __half bsm[128 * 136];
    __shared__ union {
        __half a[64 * 136];
        float c[64 * 132];
    } sm;
    int t = threadIdx.x;
    int rowBase = blockIdx.x * 64;

    // stage W (128x128 fp16) into smem, ldm 136
    {
        int r = t >> 1;               // 0..127
        int c0 = (t & 1) * 64;        // 0 or 64
        const uint4* src = (const uint4*)(Wh + r * DIM + c0);
        uint4* dst = (uint4*)(&bsm[r * 136 + c0]);
        #pragma unroll
        for (int i = 0; i < 8; i++) dst[i] = src[i];
    }
    // stage A tile (64x128 fp32 -> fp16 smem, ldm 136)
    {
        int r = t >> 2;
        int c0 = (t & 3) * 32;
        int gr = rowBase + r;
        const float4* src = (const float4*)(A + (size_t)gr * DIM + c0);
        __half* dst = &sm.a[r * 136 + c0];
        if (gr < M) {
            #pragma unroll
            for (int i = 0; i < 8; i++) {
                float4 v = src[i];
                *(__half2*)(dst + i * 4)     = __floats2half2_rn(v.x, v.y);
                *(__half2*)(dst + i * 4 + 2) = __floats2half2_rn(v.z, v.w);
            }
        } else {
            #pragma unroll
            for (int i = 0; i < 8; i++) {
                *(__half2*)(dst + i * 4)     = __half2half2(__float2half(0.f));
                *(__half2*)(dst + i * 4 + 2) = __half2half2(__float2half(0.f));
            }
        }
    }
    __syncthreads();

    int warpId = t >> 5;
    int wr = warpId & 3;
    int wc = warpId >> 2;

    wmma::fragment<wmma::accumulator, 16, 16, 16, float> cf[4];
    #pragma unroll
    for (int j = 0; j < 4; j++) wmma::fill_fragment(cf[j], 0.f);

    #pragma unroll
    for (int k0 = 0; k0 < 8; k0++) {
        wmma::fragment<wmma::matrix_a, 16, 16, 16, __half, wmma::row_major> af;
        wmma::load_matrix_sync(af, &sm.a[(wr * 16) * 136 + k0 * 16], 136);
        #pragma unroll
        for (int j = 0; j < 4; j++) {
            wmma::fragment<wmma::matrix_b, 16, 16, 16, __half, wmma::row_major> bf;
            wmma::load_matrix_sync(bf, &bsm[(k0 * 16) * 136 + wc * 64 + j * 16], 136);
            wmma::mma_sync(cf[j], af, bf, cf[j]);
        }
    }
    __syncthreads();

    #pragma unroll
    for (int j = 0; j < 4; j++)
        wmma::store_matrix_sync(&sm.c[(wr * 16) * 132 + wc * 64 + j * 16], cf[j], 132,
                                wmma::mem_row_major);
    __syncthreads();

    {
        int r = t >> 2;
        int c0 = (t & 3) * 32;
        int gr = rowBase + r;
        if (gr < M) {
            const float* src = &sm.c[r * 132 + c0];
            __half2* dst = (__half2*)(C + (size_t)gr * DIM + c0);
            #pragma unroll
            for (int i = 0; i < 16; i++)
                dst[i] = __floats2half2_rn(src[2 * i], src[2 * i + 1]);
        }
    }
}

// ---------------- fused softmax-stats + aggregation + bias + ELU ----------------
__global__ void __launch_bounds__(256)
fusedAggK(const int* __restrict__ off, const int* __restrict__ csrc,
          const float4* __restrict__ as4, const float* __restrict__ as1,
          const float4* __restrict__ ad,
          const __half* __restrict__ hs, const float* __restrict__ bias,
          float4* __restrict__ out, int n) {
    __shared__ float see[8][MAXDEG][4];
    __shared__ int ssrc[8][MAXDEG];
    int w = threadIdx.x >> 5;
    int lane = threadIdx.x & 31;
    int d = blockIdx.x * 8 + w;
    if (d >= n) return;

    int beg = off[d], end = off[d + 1];
    int deg = end - beg;
    bool cached = (deg <= MAXDEG);

    float4 adv = ad[d];
    float adh4[4] = {adv.x, adv.y, adv.z, adv.w};
    float m[4] = {-1e30f, -1e30f, -1e30f, -1e30f};
    float s[4] = {0.f, 0.f, 0.f, 0.f};

    // pass 1: per-lane online softmax stats, cache logits + src
    for (int i = lane; i < deg; i += 32) {
        int src = csrc[beg + i];
        float4 av = as4[src];
        float ev[4] = {av.x + adh4[0], av.y + adh4[1], av.z + adh4[2], av.w + adh4[3]};
        float ee[4];
        #pragma unroll
        for (int h = 0; h < 4; h++) {
            float e = ev[h] > 0.f ? ev[h] : 0.2f * ev[h];
            ee[h] = e;
            if (e > m[h]) {
                s[h] = s[h] * __expf(m[h] - e) + 1.f;
                m[h] = e;
            } else {
                s[h] += __expf(e - m[h]);
            }
        }
        if (cached) {
            ssrc[w][i] = src;
            *(float4*)(&see[w][i][0]) = make_float4(ee[0], ee[1], ee[2], ee[3]);
        }
    }
    // warp merge of (m, s)
    #pragma unroll
    for (int o = 16; o > 0; o >>= 1) {
        #pragma unroll
        for (int h = 0; h < 4; h++) {
            float om = __shfl_xor_sync(0xffffffffu, m[h], o);
            float os = __shfl_xor_sync(0xffffffffu, s[h], o);
            float nm = fmaxf(m[h], om);
            s[h] = s[h] * __expf(m[h] - nm) + os * __expf(om - nm);
            m[h] = nm;
        }
    }
    float rAll[4];
    #pragma unroll
    for (int h = 0; h < 4; h++) rAll[h] = 1.f / (s[h] + 1e-16f);

    // pass 1.5: lane-parallel weight precompute (logits -> final weights in smem)
    if (cached) {
        for (int i = lane; i < deg; i += 32) {
            float4 e4 = *(float4*)(&see[w][i][0]);
            e4.x = __expf(e4.x - m[0]) * rAll[0];
            e4.y = __expf(e4.y - m[1]) * rAll[1];
            e4.z = __expf(e4.z - m[2]) * rAll[2];
            e4.w = __expf(e4.w - m[3]) * rAll[3];
            *(float4*)(&see[w][i][0]) = e4;
        }
    }
    __syncwarp();

    int h = lane >> 3;
    float mh = m[h];
    float rh = rAll[h];
    float adh = adh4[h];

    // pass 2: weighted fp16 gather-accumulate
    float4 acc = make_float4(0.f, 0.f, 0.f, 0.f);
    for (int e = 0; e < deg; e++) {
        int src;
        float wgt;
        if (cached) {
            src = ssrc[w][e];
            wgt = see[w][e][h];
        } else {
            src = csrc[beg + e];
            float a = __ldg(&as1[src * 4 + h]);
            float ev = a + adh;
            float ee = ev > 0.f ? ev : 0.2f * ev;
            wgt = __expf(ee - mh) * rh;
        }
        const __half2* hp = reinterpret_cast<const __half2*>(hs + src * DIM) + lane * 2;
        __half2 p0 = hp[0], p1 = hp[1];
        float2 f0 = __half22float2(p0);
        float2 f1 = __half22float2(p1);
        acc.x += wgt * f0.x;
        acc.y += wgt * f0.y;
        acc.z += wgt * f1.x;
        acc.w += wgt * f1.y;
    }
    float4 b = *(const float4*)(bias + lane * 4);
    acc.x += b.x; acc.y += b.y; acc.z += b.z; acc.w += b.w;
    acc.x = acc.x > 0.f ? acc.x : expm1f(acc.x);
    acc.y = acc.y > 0.f ? acc.y : expm1f(acc.y);
    acc.z = acc.z > 0.f ? acc.z : expm1f(acc.z);
    acc.w = acc.w > 0.f ? acc.w : expm1f(acc.w);
    out[d * 32 + lane] = acc;
}

// ---------------- driver ----------------
extern "C" void kernel_launch(void* const* d_in, const int* in_sizes, int n_in,
                              void* d_out, int out_size) {
    const float* x_food  = (const float*)d_in[0];
    const float* x_nut   = (const float*)d_in[1];
    const float* WsrcFN  = (const float*)d_in[2];
    const float* WdstFN  = (const float*)d_in[3];
    const float* aSrcFN  = (const float*)d_in[4];
    const float* aDstFN  = (const float*)d_in[5];
    const float* biasFN  = (const float*)d_in[6];
    const float* WsrcNF  = (const float*)d_in[7];
    const float* WdstNF  = (const float*)d_in[8];
    const float* aSrcNF  = (const float*)d_in[9];
    const float* aDstNF  = (const float*)d_in[10];
    const float* biasNF  = (const float*)d_in[11];
    const int*   ei_fn   = (const int*)d_in[12];
    const int*   ei_nf   = (const int*)d_in[13];
    float* out = (float*)d_out;

    int NF = in_sizes[0] / DIM;
    int NN = in_sizes[1] / DIM;
    int E  = in_sizes[12] / 2;

    __half *hsA, *hsB, *Wh;
    float *hfood, *hnut, *asA, *adA, *asB, *adB, *uv;
    int *deg, *cur, *offA, *offB, *srcA, *srcB;
    cudaGetSymbolAddress((void**)&hsA, g_hsA);
    cudaGetSymbolAddress((void**)&hsB, g_hsB);
    cudaGetSymbolAddress((void**)&Wh, g_Wh);
    cudaGetSymbolAddress((void**)&hfood, g_hfood);
    cudaGetSymbolAddress((void**)&hnut, g_hnut);
    cudaGetSymbolAddress((void**)&asA, g_asA);
    cudaGetSymbolAddress((void**)&adA, g_adA);
    cudaGetSymbolAddress((void**)&asB, g_asB);
    cudaGetSymbolAddress((void**)&adB, g_adB);
    cudaGetSymbolAddress((void**)&uv, g_uv);
    cudaGetSymbolAddress((void**)&deg, g_deg);
    cudaGetSymbolAddress((void**)&cur, g_cur);
    cudaGetSymbolAddress((void**)&offA, g_offA);
    cudaGetSymbolAddress((void**)&offB, g_offB);
    cudaGetSymbolAddress((void**)&srcA, g_srcA);
    cudaGetSymbolAddress((void**)&srcB, g_srcB);

    int* degA = deg;
    int* degB = deg + MAXN;
    int* curA = cur;
    int* curB = cur + MAXN;

    int warpBlk_NN = (NN + 7) / 8;
    int warpBlk_NF = (NF + 7) / 8;
    int gemmBlk_NF = (NF + 63) / 64;
    int gemmBlk_NN = (NN + 63) / 64;

    // static streams/events (created on first, non-captured, correctness call)
    static cudaStream_t s1 = nullptr, s2 = nullptr;
    static cudaEvent_t eR, eUW, eCA, eAl0, eB0, eA0, eAl1, eB1;
    if (!s1) {
        cudaStreamCreateWithFlags(&s1, cudaStreamNonBlocking);
        cudaStreamCreateWithFlags(&s2, cudaStreamNonBlocking);
        cudaEventCreateWithFlags(&eR,   cudaEventDisableTiming);
        cudaEventCreateWithFlags(&eUW,  cudaEventDisableTiming);
        cudaEventCreateWithFlags(&eCA,  cudaEventDisableTiming);
        cudaEventCreateWithFlags(&eAl0, cudaEventDisableTiming);
        cudaEventCreateWithFlags(&eB0,  cudaEventDisableTiming);
        cudaEventCreateWithFlags(&eA0,  cudaEventDisableTiming);
        cudaEventCreateWithFlags(&eAl1, cudaEventDisableTiming);
        cudaEventCreateWithFlags(&eB1,  cudaEventDisableTiming);
    }

    // layer-0 / layer-1 parameter pointers
    const float* v_fn0 = uv + 0 * 2048 + 0 * 1024 + 0 * 512;
    const float* u_fn0 = uv + 0 * 2048 + 0 * 1024 + 1 * 512;
    const float* v_nf0 = uv + 0 * 2048 + 1 * 1024 + 0 * 512;
    const float* u_nf0 = uv + 0 * 2048 + 1 * 1024 + 1 * 512;
    const float* v_fn1 = uv + 1 * 2048 + 0 * 1024 + 0 * 512;
    const float* u_fn1 = uv + 1 * 2048 + 0 * 1024 + 1 * 512;
    const float* v_nf1 = uv + 1 * 2048 + 1 * 1024 + 0 * 512;
    const float* u_nf1 = uv + 1 * 2048 + 1 * 1024 + 1 * 512;
    const __half* Wh_fn0 = Wh + 0 * DIM * DIM;
    const __half* Wh_fn1 = Wh + 1 * DIM * DIM;
    const __half* Wh_nf0 = Wh + 2 * DIM * DIM;
    const __half* Wh_nf1 = Wh + 3 * DIM * DIM;
    float* out_food = out;
    float* out_nut  = out + (size_t)NF * DIM;

    // ---- fork ----
    cudaEventRecord(eR, 0);
    cudaStreamWaitEvent(s1, eR, 0);
    cudaStreamWaitEvent(s2, eR, 0);

    // S0: weights (launches 0,1)
    convWK<<<(4 * DIM * DIM + 255) / 256, 256>>>(WsrcFN, WsrcNF, Wh);
    uvK<<<16, 256>>>(WsrcFN, WdstFN, aSrcFN, aDstFN, WsrcNF, WdstNF, aSrcNF, aDstNF, uv);
    cudaEventRecord(eUW, 0);

    // S1: CSR-A start (launches 2,3)
    histK<<<1024, 256, 0, s1>>>(ei_fn + E, degA, E);
    scanK<<<1, 1024, 0, s1>>>(degA, offA, curA, NN);

    // S0: layer-0 fn GEMM (launch 4 — profiled slot)
    gemmTC<<<gemmBlk_NF, 256>>>(x_food, Wh_fn0, hsA, NF);

    // S1: CSR-A finish
    fillK<<<1024, 256, 0, s1>>>(ei_fn, curA, srcA, E);
    sortZK<<<(NN + 7) / 8, 256, 0, s1>>>(offA, srcA, NN, degA);
    cudaEventRecord(eCA, s1);

    // S2: CSR-B
    histK<<<1024, 256, 0, s2>>>(ei_nf + E, degB, E);
    scanK<<<1, 1024, 0, s2>>>(degB, offB, curB, NF);
    fillK<<<1024, 256, 0, s2>>>(ei_nf, curB, srcB, E);
    sortZK<<<(NF + 7) / 8, 256, 0, s2>>>(offB, srcB, NF, degB);

    // S0: layer-0 alphas
    alphaK<<<warpBlk_NF, 256>>>((const float4*)x_food, v_fn0, u_nf0,
                                (float4*)asA, (float4*)adB, NF);
    alphaK<<<warpBlk_NN, 256>>>((const float4*)x_nut, v_nf0, u_fn0,
                                (float4*)asB, (float4*)adA, NN);
    cudaEventRecord(eAl0, 0);

    // S2: layer-0 nf chain (gemm needs convW; agg needs alphas + CSR-B + hsB)
    cudaStreamWaitEvent(s2, eUW, 0);
    gemmTC<<<gemmBlk_NN, 256, 0, s2>>>(x_nut, Wh_nf0, hsB, NN);
    cudaStreamWaitEvent(s2, eAl0, 0);
    fusedAggK<<<warpBlk_NF, 256, 0, s2>>>(offB, srcB, (const float4*)asB, asB,
                                          (const float4*)adB, hsB, biasNF,
                                          (float4*)hfood, NF);
    cudaEventRecord(eB0, s2);

    // S0: layer-0 fn agg (needs CSR-A)
    cudaStreamWaitEvent(0, eCA, 0);
    fusedAggK<<<warpBlk_NN, 256>>>(offA, srcA, (const float4*)asA, asA,
                                   (const float4*)adA, hsA, biasFN,
                                   (float4*)hnut, NN);
    cudaEventRecord(eA0, 0);

    // S0: layer-1 (needs hfood from S2)
    cudaStreamWaitEvent(0, eB0, 0);
    alphaK<<<warpBlk_NF, 256>>>((const float4*)hfood, v_fn1, u_nf1,
                                (float4*)asA, (float4*)adB, NF);
    alphaK<<<warpBlk_NN, 256>>>((const float4*)hnut, v_nf1, u_fn1,
                                (float4*)asB, (float4*)adA, NN);
    cudaEventRecord(eAl1, 0);
    gemmTC<<<gemmBlk_NF, 256>>>(hfood, Wh_fn1, hsA, NF);
    fusedAggK<<<warpBlk_NN, 256>>>(offA, srcA, (const float4*)asA, asA,
                                   (const float4*)adA, hsA, biasFN + DIM,
                                   (float4*)out_nut, NN);

    // S2: layer-1 nf chain (gemm needs hnut from S0's aggA0)
    cudaStreamWaitEvent(s2, eA0, 0);
    gemmTC<<<gemmBlk_NN, 256, 0, s2>>>(hnut, Wh_nf1, hsB, NN);
    cudaStreamWaitEvent(s2, eAl1, 0);
    fusedAggK<<<warpBlk_NF, 256, 0, s2>>>(offB, srcB, (const float4*)asB, asB,
                                          (const float4*)adB, hsB, biasNF + DIM,
                                          (float4*)out_food, NF);
    cudaEventRecord(eB1, s2);

    // ---- join ----
    cudaStreamWaitEvent(0, eB1, 0);
}

// round 5
// speedup vs baseline: 1.5639x; 1.0971x over previous
#include <cuda_runtime.h>
#include <cuda_fp16.h>
#include <mma.h>
#include <math.h>
#include <limits.h>

using namespace nvcuda;

#define DIM 128
#define NH 4
#define MAXN 50048
#define MAXE 800032
#define MAXDEG 96
#define SCANB 256

// ---------------- scratch (static device globals; no allocation) ----------------
__device__ __half g_hsA[MAXN * DIM];    // fn-relation messages
__device__ __half g_hsB[MAXN * DIM];    // nf-relation messages
__device__ __half g_Wh[4 * DIM * DIM];  // fp16 Wsrc: [rel][l][128*128]
__device__ float g_hfood[MAXN * DIM];
__device__ float g_hnut[MAXN * DIM];
__device__ float g_asA[MAXN * NH];
__device__ float g_adA[MAXN * NH];
__device__ float g_asB[MAXN * NH];
__device__ float g_adB[MAXN * NH];
__device__ float g_uv[4096];
__device__ int   g_deg[2 * MAXN];       // zero-initialized; re-zeroed by sortZK epilogue
__device__ int   g_cur[2 * MAXN];
__device__ int   g_bsum[2 * 256];       // block partial sums for hierarchical scan
__device__ int   g_offA[MAXN + 1];
__device__ int   g_offB[MAXN + 1];
__device__ int   g_srcA[MAXE];
__device__ int   g_srcB[MAXE];

// ---------------- CSR build (per relation, stream-parallel) ----------------
__global__ void histK(const int* __restrict__ dst, int* __restrict__ deg, int E) {
    int i = blockIdx.x * blockDim.x + threadIdx.x;
    int stride = gridDim.x * blockDim.x;
    for (; i < E; i += stride) atomicAdd(&deg[dst[i]], 1);
}

// ---- hierarchical scan: (1) per-block sums ----
__global__ void scanSumK(const int* __restrict__ deg, int* __restrict__ bsum, int n) {
    __shared__ int wsum[8];
    int t = threadIdx.x;
    int i = blockIdx.x * SCANB + t;
    int v = (i < n) ? deg[i] : 0;
    #pragma unroll
    for (int o = 16; o > 0; o >>= 1) v += __shfl_down_sync(0xffffffffu, v, o);
    if ((t & 31) == 0) wsum[t >> 5] = v;
    __syncthreads();
    if (t == 0) {
        int s = 0;
        #pragma unroll
        for (int w = 0; w < 8; w++) s += wsum[w];
        bsum[blockIdx.x] = s;
    }
}

// ---- (2) single-block exclusive scan of block sums (nb <= 256) ----
__global__ void scanTopK(int* __restrict__ bsum, int nb) {
    __shared__ int sh[SCANB];
    int t = threadIdx.x;
    int v = (t < nb) ? bsum[t] : 0;
    sh[t] = v;
    __syncthreads();
    #pragma unroll
    for (int d = 1; d < SCANB; d <<= 1) {
        int x = 0;
        if (t >= d) x = sh[t - d];
        __syncthreads();
        if (t >= d) sh[t] += x;
        __syncthreads();
    }
    if (t < nb) bsum[t] = sh[t] - v;  // exclusive
}

// ---- (3) per-block scan + apply: writes off, cur, off[n] ----
__global__ void scanApplyK(const int* __restrict__ deg, const int* __restrict__ bsum,
                           int* __restrict__ off, int* __restrict__ cur, int n) {
    __shared__ int wsum[8];
    int t = threadIdx.x;
    int lane = t & 31, wid = t >> 5;
    int i = blockIdx.x * SCANB + t;
    int v = (i < n) ? deg[i] : 0;
    int incl = v;
    #pragma unroll
    for (int o = 1; o < 32; o <<= 1) {
        int x = __shfl_up_sync(0xffffffffu, incl, o);
        if (lane >= o) incl += x;
    }
    if (lane == 31) wsum[wid] = incl;
    __syncthreads();
    if (wid == 0 && lane < 8) {
        int w = wsum[lane];
        int wi = w;
        #pragma unroll
        for (int o = 1; o < 8; o <<= 1) {
            int x = __shfl_up_sync(0xffu, wi, o);
            if (lane >= o) wi += x;
        }
        wsum[lane] = wi - w;  // exclusive warp offsets
    }
    __syncthreads();
    int excl = incl - v + wsum[wid] + bsum[blockIdx.x];
    if (i < n) {
        off[i] = excl;
        cur[i] = excl;
        if (i == n - 1) off[n] = excl + v;
    }
}

__global__ void fillK(const int* __restrict__ ei, int* __restrict__ cur,
                      int* __restrict__ csrc, int E) {
    int i = blockIdx.x * blockDim.x + threadIdx.x;
    int stride = gridDim.x * blockDim.x;
    for (; i < E; i += stride) {
        int pos = atomicAdd(&cur[ei[E + i]], 1);
        csrc[pos] = ei[i];
    }
}

// warp-per-bucket bitonic sort + epilogue zeroing of deg for next graph replay
__global__ void __launch_bounds__(256)
sortZK(const int* __restrict__ off, int* __restrict__ csrc, int n,
       int* __restrict__ deg) {
    for (int i = blockIdx.x * blockDim.x + threadIdx.x; i < n;
         i += gridDim.x * blockDim.x) deg[i] = 0;

    int w = (blockIdx.x * blockDim.x + threadIdx.x) >> 5;
    int lane = threadIdx.x & 31;
    if (w >= n) return;
    int beg = off[w];
    int cnt = off[w + 1] - beg;
    if (cnt <= 1) return;
    if (cnt <= 32) {
        int v0 = (lane < cnt) ? csrc[beg + lane] : INT_MAX;
        #pragma unroll
        for (int size = 2; size <= 32; size <<= 1) {
            #pragma unroll
            for (int stride = size >> 1; stride > 0; stride >>= 1) {
                int p0 = __shfl_xor_sync(0xffffffffu, v0, stride);
                bool up0 = (size == 32) ? true : ((lane & size) == 0);
                bool lower = ((lane & stride) == 0);
                v0 = (lower == up0) ? min(v0, p0) : max(v0, p0);
            }
        }
        if (lane < cnt) csrc[beg + lane] = v0;
    } else if (cnt <= 64) {
        int v0 = (lane < cnt) ? csrc[beg + lane] : INT_MAX;
        int v1 = (32 + lane < cnt) ? csrc[beg + 32 + lane] : INT_MAX;
        #pragma unroll
        for (int size = 2; size <= 64; size <<= 1) {
            #pragma unroll
            for (int stride = size >> 1; stride > 0; stride >>= 1) {
                if (stride == 32) {
                    int lo = min(v0, v1), hi = max(v0, v1);
                    v0 = lo; v1 = hi;
                } else {
                    int p0 = __shfl_xor_sync(0xffffffffu, v0, stride);
                    int p1 = __shfl_xor_sync(0xffffffffu, v1, stride);
                    bool up0, up1;
                    if (size == 64)      { up0 = true; up1 = true; }
                    else if (size == 32) { up0 = true; up1 = false; }
                    else { up0 = ((lane & size) == 0); up1 = up0; }
                    bool lower = ((lane & stride) == 0);
                    v0 = (lower == up0) ? min(v0, p0) : max(v0, p0);
                    v1 = (lower == up1) ? min(v1, p1) : max(v1, p1);
                }
            }
        }
        if (lane < cnt) csrc[beg + lane] = v0;
        if (32 + lane < cnt) csrc[beg + 32 + lane] = v1;
    } else if (lane == 0) {
        int end = beg + cnt;
        for (int i = beg + 1; i < end; i++) {
            int key = csrc[i];
            int j = i - 1;
            while (j >= beg && csrc[j] > key) { csrc[j + 1] = csrc[j]; j--; }
            csrc[j + 1] = key;
        }
    }
}

// ---------------- folded attention vectors ----------------
__global__ void uvK(const float* __restrict__ WsrcFN, const float* __restrict__ WdstFN,
                    const float* __restrict__ aSrcFN, const float* __restrict__ aDstFN,
                    const float* __restrict__ WsrcNF, const float* __restrict__ WdstNF,
                    const float* __restrict__ aSrcNF, const float* __restrict__ aDstNF,
                    float* __restrict__ uv) {
    int t = blockIdx.x * blockDim.x + threadIdx.x;
    if (t >= 4096) return;
    int h = t & 3;
    int k = (t >> 2) & 127;
    int sv = (t >> 9) & 1;
    int rel = (t >> 10) & 1;
    int l = (t >> 11) & 1;
    const float* W;
    const float* att;
    if (rel == 0) { W = sv ? WdstFN : WsrcFN; att = sv ? aDstFN : aSrcFN; }
    else          { W = sv ? WdstNF : WsrcNF; att = sv ? aDstNF : aSrcNF; }
    W += l * DIM * DIM;
    att += l * NH * 32;
    float sum = 0.f;
    #pragma unroll 8
    for (int c = 0; c < 32; c++)
        sum += W[k * DIM + h * 32 + c] * att[h * 32 + c];
    uv[t] = sum;
}

// ---------------- fp16 weight conversion ----------------
__global__ void convWK(const float* __restrict__ WsrcFN, const float* __restrict__ WsrcNF,
                       __half* __restrict__ Wh) {
    int i = blockIdx.x * blockDim.x + threadIdx.x;
    if (i >= 4 * DIM * DIM) return;
    int rel = i >> 15;
    int rest = i & 32767;
    const float* W = rel ? WsrcNF : WsrcFN;
    Wh[i] = __float2half(W[rest]);
}

// ---------------- alpha projections: as = x @ v, ad = x @ u ----------------
__global__ void alphaK(const float4* __restrict__ x, const float* __restrict__ vmat,
                       const float* __restrict__ umat, float4* __restrict__ asOut,
                       float4* __restrict__ adOut, int n) {
    __shared__ float sv[512];
    __shared__ float su[512];
    int t = threadIdx.x;
    for (int i = t; i < 512; i += blockDim.x) { sv[i] = vmat[i]; su[i] = umat[i]; }
    __syncthreads();
    int warp = (blockIdx.x * blockDim.x + t) >> 5;
    int lane = t & 31;
    if (warp >= n) return;
    float4 xv = x[warp * 32 + lane];
    float xj[4] = {xv.x, xv.y, xv.z, xv.w};
    float pa[4] = {0, 0, 0, 0}, pd[4] = {0, 0, 0, 0};
    int j0 = lane * 4;
    #pragma unroll
    for (int j = 0; j < 4; j++) {
        #pragma unroll
        for (int h = 0; h < 4; h++) {
            pa[h] += xj[j] * sv[(j0 + j) * 4 + h];
            pd[h] += xj[j] * su[(j0 + j) * 4 + h];
        }
    }
    #pragma unroll
    for (int o = 16; o > 0; o >>= 1) {
        #pragma unroll
        for (int h = 0; h < 4; h++) {
            pa[h] += __shfl_down_sync(0xffffffffu, pa[h], o);
            pd[h] += __shfl_down_sync(0xffffffffu, pd[h], o);
        }
    }
    if (lane == 0) {
        asOut[warp] = make_float4(pa[0], pa[1], pa[2], pa[3]);
        adOut[warp] = make_float4(pd[0], pd[1], pd[2], pd[3]);
    }
}

// ---------------- tensor-core GEMM: C[M,128] = A[M,128] @ W[128,128] ----------------
__global__ void __launch_bounds__(256)
gemmTC(const float* __restrict__ A, const __half* __restrict__ Wh,
       __half* __restrict__ C, int M) {
    __shared__ __half bsm[128 * 136];
    __shared__ union {
        __half a[64 * 136];
        float c[64 * 132];
    } sm;
    int t = threadIdx.x;
    int rowBase = blockIdx.x * 64;

    {
        int r = t >> 1;
        int c0 = (t & 1) * 64;
        const uint4* src = (const uint4*)(Wh + r * DIM + c0);
        uint4* dst = (uint4*)(&bsm[r * 136 + c0]);
        #pragma unroll
        for (int i = 0; i < 8; i++) dst[i] = src[i];
    }
    {
        int r = t >> 2;
        int c0 = (t & 3) * 32;
        int gr = rowBase + r;
        const float4* src = (const float4*)(A + (size_t)gr * DIM + c0);
        __half* dst = &sm.a[r * 136 + c0];
        if (gr < M) {
            #pragma unroll
            for (int i = 0; i < 8; i++) {
                float4 v = src[i];
                *(__half2*)(dst + i * 4)     = __floats2half2_rn(v.x, v.y);
                *(__half2*)(dst + i * 4 + 2) = __floats2half2_rn(v.z, v.w);
            }
        } else {
            #pragma unroll
            for (int i = 0; i < 8; i++) {
                *(__half2*)(dst + i * 4)     = __half2half2(__float2half(0.f));
                *(__half2*)(dst + i * 4 + 2) = __half2half2(__float2half(0.f));
            }
        }
    }
    __syncthreads();

    int warpId = t >> 5;
    int wr = warpId & 3;
    int wc = warpId >> 2;

    wmma::fragment<wmma::accumulator, 16, 16, 16, float> cf[4];
    #pragma unroll
    for (int j = 0; j < 4; j++) wmma::fill_fragment(cf[j], 0.f);

    #pragma unroll
    for (int k0 = 0; k0 < 8; k0++) {
        wmma::fragment<wmma::matrix_a, 16, 16, 16, __half, wmma::row_major> af;
        wmma::load_matrix_sync(af, &sm.a[(wr * 16) * 136 + k0 * 16], 136);
        #pragma unroll
        for (int j = 0; j < 4; j++) {
            wmma::fragment<wmma::matrix_b, 16, 16, 16, __half, wmma::row_major> bf;
            wmma::load_matrix_sync(bf, &bsm[(k0 * 16) * 136 + wc * 64 + j * 16], 136);
            wmma::mma_sync(cf[j], af, bf, cf[j]);
        }
    }
    __syncthreads();

    #pragma unroll
    for (int j = 0; j < 4; j++)
        wmma::store_matrix_sync(&sm.c[(wr * 16) * 132 + wc * 64 + j * 16], cf[j], 132,
                                wmma::mem_row_major);
    __syncthreads();

    {
        int r = t >> 2;
        int c0 = (t & 3) * 32;
        int gr = rowBase + r;
        if (gr < M) {
            const float* src = &sm.c[r * 132 + c0];
            __half2* dst = (__half2*)(C + (size_t)gr * DIM + c0);
            #pragma unroll
            for (int i = 0; i < 16; i++)
                dst[i] = __floats2half2_rn(src[2 * i], src[2 * i + 1]);
        }
    }
}

// ---------------- fused softmax-stats + aggregation + bias + ELU ----------------
__global__ void __launch_bounds__(256)
fusedAggK(const int* __restrict__ off, const int* __restrict__ csrc,
          const float4* __restrict__ as4, const float* __restrict__ as1,
          const float4* __restrict__ ad,
          const __half* __restrict__ hs, const float* __restrict__ bias,
          float4* __restrict__ out, int n) {
    __shared__ float see[8][MAXDEG][4];
    __shared__ int ssrc[8][MAXDEG];
    int w = threadIdx.x >> 5;
    int lane = threadIdx.x & 31;
    int d = blockIdx.x * 8 + w;
    if (d >= n) return;

    int beg = off[d], end = off[d + 1];
    int deg = end - beg;
    bool cached = (deg <= MAXDEG);

    float4 adv = ad[d];
    float adh4[4] = {adv.x, adv.y, adv.z, adv.w};
    float m[4] = {-1e30f, -1e30f, -1e30f, -1e30f};
    float s[4] = {0.f, 0.f, 0.f, 0.f};

    for (int i = lane; i < deg; i += 32) {
        int src = csrc[beg + i];
        float4 av = as4[src];
        float ev[4] = {av.x + adh4[0], av.y + adh4[1], av.z + adh4[2], av.w + adh4[3]};
        float ee[4];
        #pragma unroll
        for (int h = 0; h < 4; h++) {
            float e = ev[h] > 0.f ? ev[h] : 0.2f * ev[h];
            ee[h] = e;
            if (e > m[h]) {
                s[h] = s[h] * __expf(m[h] - e) + 1.f;
                m[h] = e;
            } else {
                s[h] += __expf(e - m[h]);
            }
        }
        if (cached) {
            ssrc[w][i] = src;
            *(float4*)(&see[w][i][0]) = make_float4(ee[0], ee[1], ee[2], ee[3]);
        }
    }
    #pragma unroll
    for (int o = 16; o > 0; o >>= 1) {
        #pragma unroll
        for (int h = 0; h < 4; h++) {
            float om = __shfl_xor_sync(0xffffffffu, m[h], o);
            float os = __shfl_xor_sync(0xffffffffu, s[h], o);
            float nm = fmaxf(m[h], om);
            s[h] = s[h] * __expf(m[h] - nm) + os * __expf(om - nm);
            m[h] = nm;
        }
    }
    float rAll[4];
    #pragma unroll
    for (int h = 0; h < 4; h++) rAll[h] = 1.f / (s[h] + 1e-16f);

    if (cached) {
        for (int i = lane; i < deg; i += 32) {
            float4 e4 = *(float4*)(&see[w][i][0]);
            e4.x = __expf(e4.x - m[0]) * rAll[0];
            e4.y = __expf(e4.y - m[1]) * rAll[1];
            e4.z = __expf(e4.z - m[2]) * rAll[2];
            e4.w = __expf(e4.w - m[3]) * rAll[3];
            *(float4*)(&see[w][i][0]) = e4;
        }
    }
    __syncwarp();

    int h = lane >> 3;
    float mh = m[h];
    float rh = rAll[h];
    float adh = adh4[h];

    float4 acc = make_float4(0.f, 0.f, 0.f, 0.f);
    for (int e = 0; e < deg; e++) {
        int src;
        float wgt;
        if (cached) {
            src = ssrc[w][e];
            wgt = see[w][e][h];
        } else {
            src = csrc[beg + e];
            float a = __ldg(&as1[src * 4 + h]);
            float ev = a + adh;
            float ee = ev > 0.f ? ev : 0.2f * ev;
            wgt = __expf(ee - mh) * rh;
        }
        const __half2* hp = reinterpret_cast<const __half2*>(hs + src * DIM) + lane * 2;
        __half2 p0 = hp[0], p1 = hp[1];
        float2 f0 = __half22float2(p0);
        float2 f1 = __half22float2(p1);
        acc.x += wgt * f0.x;
        acc.y += wgt * f0.y;
        acc.z += wgt * f1.x;
        acc.w += wgt * f1.y;
    }
    float4 b = *(const float4*)(bias + lane * 4);
    acc.x += b.x; acc.y += b.y; acc.z += b.z; acc.w += b.w;
    acc.x = acc.x > 0.f ? acc.x : expm1f(acc.x);
    acc.y = acc.y > 0.f ? acc.y : expm1f(acc.y);
    acc.z = acc.z > 0.f ? acc.z : expm1f(acc.z);
    acc.w = acc.w > 0.f ? acc.w : expm1f(acc.w);
    out[d * 32 + lane] = acc;
}

// ---------------- driver ----------------
extern "C" void kernel_launch(void* const* d_in, const int* in_sizes, int n_in,
                              void* d_out, int out_size) {
    const float* x_food  = (const float*)d_in[0];
    const float* x_nut   = (const float*)d_in[1];
    const float* WsrcFN  = (const float*)d_in[2];
    const float* WdstFN  = (const float*)d_in[3];
    const float* aSrcFN  = (const float*)d_in[4];
    const float* aDstFN  = (const float*)d_in[5];
    const float* biasFN  = (const float*)d_in[6];
    const float* WsrcNF  = (const float*)d_in[7];
    const float* WdstNF  = (const float*)d_in[8];
    const float* aSrcNF  = (const float*)d_in[9];
    const float* aDstNF  = (const float*)d_in[10];
    const float* biasNF  = (const float*)d_in[11];
    const int*   ei_fn   = (const int*)d_in[12];
    const int*   ei_nf   = (const int*)d_in[13];
    float* out = (float*)d_out;

    int NF = in_sizes[0] / DIM;
    int NN = in_sizes[1] / DIM;
    int E  = in_sizes[12] / 2;

    __half *hsA, *hsB, *Wh;
    float *hfood, *hnut, *asA, *adA, *asB, *adB, *uv;
    int *deg, *cur, *bsum, *offA, *offB, *srcA, *srcB;
    cudaGetSymbolAddress((void**)&hsA, g_hsA);
    cudaGetSymbolAddress((void**)&hsB, g_hsB);
    cudaGetSymbolAddress((void**)&Wh, g_Wh);
    cudaGetSymbolAddress((void**)&hfood, g_hfood);
    cudaGetSymbolAddress((void**)&hnut, g_hnut);
    cudaGetSymbolAddress((void**)&asA, g_asA);
    cudaGetSymbolAddress((void**)&adA, g_adA);
    cudaGetSymbolAddress((void**)&asB, g_asB);
    cudaGetSymbolAddress((void**)&adB, g_adB);
    cudaGetSymbolAddress((void**)&uv, g_uv);
    cudaGetSymbolAddress((void**)&deg, g_deg);
    cudaGetSymbolAddress((void**)&cur, g_cur);
    cudaGetSymbolAddress((void**)&bsum, g_bsum);
    cudaGetSymbolAddress((void**)&offA, g_offA);
    cudaGetSymbolAddress((void**)&offB, g_offB);
    cudaGetSymbolAddress((void**)&srcA, g_srcA);
    cudaGetSymbolAddress((void**)&srcB, g_srcB);

    int* degA = deg;
    int* degB = deg + MAXN;
    int* curA = cur;
    int* curB = cur + MAXN;
    int* bsumA = bsum;
    int* bsumB = bsum + 256;

    int warpBlk_NN = (NN + 7) / 8;
    int warpBlk_NF = (NF + 7) / 8;
    int gemmBlk_NF = (NF + 63) / 64;
    int gemmBlk_NN = (NN + 63) / 64;
    int scanBlkA = (NN + SCANB - 1) / SCANB;
    int scanBlkB = (NF + SCANB - 1) / SCANB;

    static cudaStream_t s1 = nullptr, s2 = nullptr;
    static cudaEvent_t eR, eUW, eCA, eAl0, eB0, eA0, eAl1, eB1;
    if (!s1) {
        cudaStreamCreateWithFlags(&s1, cudaStreamNonBlocking);
        cudaStreamCreateWithFlags(&s2, cudaStreamNonBlocking);
        cudaEventCreateWithFlags(&eR,   cudaEventDisableTiming);
        cudaEventCreateWithFlags(&eUW,  cudaEventDisableTiming);
        cudaEventCreateWithFlags(&eCA,  cudaEventDisableTiming);
        cudaEventCreateWithFlags(&eAl0, cudaEventDisableTiming);
        cudaEventCreateWithFlags(&eB0,  cudaEventDisableTiming);
        cudaEventCreateWithFlags(&eA0,  cudaEventDisableTiming);
        cudaEventCreateWithFlags(&eAl1, cudaEventDisableTiming);
        cudaEventCreateWithFlags(&eB1,  cudaEventDisableTiming);
    }

    const float* v_fn0 = uv + 0 * 2048 + 0 * 1024 + 0 * 512;
    const float* u_fn0 = uv + 0 * 2048 + 0 * 1024 + 1 * 512;
    const float* v_nf0 = uv + 0 * 2048 + 1 * 1024 + 0 * 512;
    const float* u_nf0 = uv + 0 * 2048 + 1 * 1024 + 1 * 512;
    const float* v_fn1 = uv + 1 * 2048 + 0 * 1024 + 0 * 512;
    const float* u_fn1 = uv + 1 * 2048 + 0 * 1024 + 1 * 512;
    const float* v_nf1 = uv + 1 * 2048 + 1 * 1024 + 0 * 512;
    const float* u_nf1 = uv + 1 * 2048 + 1 * 1024 + 1 * 512;
    const __half* Wh_fn0 = Wh + 0 * DIM * DIM;
    const __half* Wh_fn1 = Wh + 1 * DIM * DIM;
    const __half* Wh_nf0 = Wh + 2 * DIM * DIM;
    const __half* Wh_nf1 = Wh + 3 * DIM * DIM;
    float* out_food = out;
    float* out_nut  = out + (size_t)NF * DIM;

    // ---- fork ----
    cudaEventRecord(eR, 0);
    cudaStreamWaitEvent(s1, eR, 0);
    cudaStreamWaitEvent(s2, eR, 0);

    // S0: weights
    convWK<<<(4 * DIM * DIM + 255) / 256, 256>>>(WsrcFN, WsrcNF, Wh);
    uvK<<<16, 256>>>(WsrcFN, WdstFN, aSrcFN, aDstFN, WsrcNF, WdstNF, aSrcNF, aDstNF, uv);
    cudaEventRecord(eUW, 0);

    // S1: CSR-A
    histK<<<1024, 256, 0, s1>>>(ei_fn + E, degA, E);
    scanSumK<<<scanBlkA, SCANB, 0, s1>>>(degA, bsumA, NN);
    scanTopK<<<1, SCANB, 0, s1>>>(bsumA, scanBlkA);
    scanApplyK<<<scanBlkA, SCANB, 0, s1>>>(degA, bsumA, offA, curA, NN);
    fillK<<<1024, 256, 0, s1>>>(ei_fn, curA, srcA, E);
    sortZK<<<(NN + 7) / 8, 256, 0, s1>>>(offA, srcA, NN, degA);
    cudaEventRecord(eCA, s1);

    // S2: CSR-B
    histK<<<1024, 256, 0, s2>>>(ei_nf + E, degB, E);
    scanSumK<<<scanBlkB, SCANB, 0, s2>>>(degB, bsumB, NF);
    scanTopK<<<1, SCANB, 0, s2>>>(bsumB, scanBlkB);
    scanApplyK<<<scanBlkB, SCANB, 0, s2>>>(degB, bsumB, offB, curB, NF);
    fillK<<<1024, 256, 0, s2>>>(ei_nf, curB, srcB, E);
    sortZK<<<(NF + 7) / 8, 256, 0, s2>>>(offB, srcB, NF, degB);

    // S0: layer-0 fn GEMM + alphas
    gemmTC<<<gemmBlk_NF, 256>>>(x_food, Wh_fn0, hsA, NF);
    alphaK<<<warpBlk_NF, 256>>>((const float4*)x_food, v_fn0, u_nf0,
                                (float4*)asA, (float4*)adB, NF);
    alphaK<<<warpBlk_NN, 256>>>((const float4*)x_nut, v_nf0, u_fn0,
                                (float4*)asB, (float4*)adA, NN);
    cudaEventRecord(eAl0, 0);

    // S2: layer-0 nf chain
    cudaStreamWaitEvent(s2, eUW, 0);
    gemmTC<<<gemmBlk_NN, 256, 0, s2>>>(x_nut, Wh_nf0, hsB, NN);
    cudaStreamWaitEvent(s2, eAl0, 0);
    fusedAggK<<<warpBlk_NF, 256, 0, s2>>>(offB, srcB, (const float4*)asB, asB,
                                          (const float4*)adB, hsB, biasNF,
                                          (float4*)hfood, NF);
    cudaEventRecord(eB0, s2);

    // S0: layer-0 fn agg
    cudaStreamWaitEvent(0, eCA, 0);
    fusedAggK<<<warpBlk_NN, 256>>>(offA, srcA, (const float4*)asA, asA,
                                   (const float4*)adA, hsA, biasFN,
                                   (float4*)hnut, NN);
    cudaEventRecord(eA0, 0);

    // S0: layer-1
    cudaStreamWaitEvent(0, eB0, 0);
    alphaK<<<warpBlk_NF, 256>>>((const float4*)hfood, v_fn1, u_nf1,
                                (float4*)asA, (float4*)adB, NF);
    alphaK<<<warpBlk_NN, 256>>>((const float4*)hnut, v_nf1, u_fn1,
                                (float4*)asB, (float4*)adA, NN);
    cudaEventRecord(eAl1, 0);
    gemmTC<<<gemmBlk_NF, 256>>>(hfood, Wh_fn1, hsA, NF);
    fusedAggK<<<warpBlk_NN, 256>>>(offA, srcA, (const float4*)asA, asA,
                                   (const float4*)adA, hsA, biasFN + DIM,
                                   (float4*)out_nut, NN);

    // S2: layer-1 nf chain
    cudaStreamWaitEvent(s2, eA0, 0);
    gemmTC<<<gemmBlk_NN, 256, 0, s2>>>(hnut, Wh_nf1, hsB, NN);
    cudaStreamWaitEvent(s2, eAl1, 0);
    fusedAggK<<<warpBlk_NF, 256, 0, s2>>>(offB, srcB, (const float4*)asB, asB,
                                          (const float4*)adB, hsB, biasNF + DIM,
                                          (float4*)out_food, NF);
    cudaEventRecord(eB1, s2);

    // ---- join ----
    cudaStreamWaitEvent(0, eB1, 0);
}